// round 3
// baseline (speedup 1.0000x reference)
#include <cuda_runtime.h>
#include <stdint.h>
#include <math.h>

#define Tq 1024
#define Bq 8
#define Dq 1024
#define NH 16
#define DH 64
#define TB (Tq*Bq)       /* 8192 rows */
#define ND (NH*DH)       /* 1024 */
#define N3 (3*ND)        /* 3072 */
#define ZN (Bq*NH)       /* 128 */

// ---- static scratch (zero-initialized; masked region of g_S never written) ----
__device__ float g_q[(size_t)ZN*Tq*DH];     // [b][n][t][d]
__device__ float g_k[(size_t)ZN*Tq*DH];
__device__ float g_v[(size_t)ZN*Tq*DH];
__device__ float g_av[(size_t)TB*ND];       // [t*B+b][n*64+d]
__device__ float g_S[(size_t)ZN*Tq*Tq];     // final probs, [z][i][j] (masked = 0)

// ---- tf32 helpers ----
__device__ __forceinline__ uint32_t f2tf(float x) {
    uint32_t y;
    asm("cvt.rna.tf32.f32 %0, %1;" : "=r"(y) : "f"(x));
    return y;
}
__device__ __forceinline__ void mma8(float c[4],
                                     uint32_t a0, uint32_t a1, uint32_t a2, uint32_t a3,
                                     uint32_t b0, uint32_t b1) {
    asm volatile("mma.sync.aligned.m16n8k8.row.col.f32.tf32.tf32.f32 "
                 "{%0,%1,%2,%3}, {%4,%5,%6,%7}, {%8,%9}, {%0,%1,%2,%3};\n"
                 : "+f"(c[0]), "+f"(c[1]), "+f"(c[2]), "+f"(c[3])
                 : "r"(a0), "r"(a1), "r"(a2), "r"(a3), "r"(b0), "r"(b1));
}

// ============================================================================
// QKV GEMM (tf32 MMA): C[8192,3072] = (input+pos_enc)[8192,1024] @ W[1024,3072]
// ============================================================================
__global__ __launch_bounds__(256) void qkv_gemm(const float* __restrict__ inp,
                                                const float* __restrict__ pe,
                                                const float* __restrict__ W) {
    __shared__ __align__(16) uint32_t As[128][36];
    __shared__ __align__(16) uint32_t Bs[32][136];
    const int tx = threadIdx.x;
    const int warp = tx >> 5, lane = tx & 31;
    const int g = lane >> 2, tg = lane & 3;
    const int wm = (warp >> 2) * 64;
    const int wn = (warp & 3) * 32;
    const int m0 = blockIdx.y * 128, n0 = blockIdx.x * 128;

    const int la_m = tx >> 3, la_k = (tx & 7) << 2;
    const int lb_k = tx >> 5, lb_n = (tx & 31) << 2;

    float acc[4][4][4];
#pragma unroll
    for (int mi = 0; mi < 4; mi++)
#pragma unroll
        for (int ni = 0; ni < 4; ni++)
#pragma unroll
            for (int r = 0; r < 4; r++) acc[mi][ni][r] = 0.f;

    for (int k0 = 0; k0 < Dq; k0 += 32) {
#pragma unroll
        for (int rr = 0; rr < 4; rr++) {
            int m = la_m + rr * 32;
            size_t gi = (size_t)(m0 + m) * Dq + k0 + la_k;
            float4 a = *(const float4*)(inp + gi);
            float4 p = *(const float4*)(pe + gi);
            uint4 v;
            v.x = f2tf(a.x + p.x); v.y = f2tf(a.y + p.y);
            v.z = f2tf(a.z + p.z); v.w = f2tf(a.w + p.w);
            *(uint4*)&As[m][la_k] = v;
        }
#pragma unroll
        for (int rr = 0; rr < 4; rr++) {
            int kk = lb_k + rr * 8;
            float4 b = *(const float4*)(W + (size_t)(k0 + kk) * N3 + n0 + lb_n);
            uint4 v;
            v.x = f2tf(b.x); v.y = f2tf(b.y); v.z = f2tf(b.z); v.w = f2tf(b.w);
            *(uint4*)&Bs[kk][lb_n] = v;
        }
        __syncthreads();
#pragma unroll
        for (int ks = 0; ks < 32; ks += 8) {
            uint32_t a[4][4], b[4][2];
#pragma unroll
            for (int mi = 0; mi < 4; mi++) {
                int r = wm + mi * 16 + g;
                a[mi][0] = As[r][ks + tg];
                a[mi][1] = As[r + 8][ks + tg];
                a[mi][2] = As[r][ks + tg + 4];
                a[mi][3] = As[r + 8][ks + tg + 4];
            }
#pragma unroll
            for (int ni = 0; ni < 4; ni++) {
                int c = wn + ni * 8 + g;
                b[ni][0] = Bs[ks + tg][c];
                b[ni][1] = Bs[ks + tg + 4][c];
            }
#pragma unroll
            for (int mi = 0; mi < 4; mi++)
#pragma unroll
                for (int ni = 0; ni < 4; ni++)
                    mma8(acc[mi][ni], a[mi][0], a[mi][1], a[mi][2], a[mi][3],
                         b[ni][0], b[ni][1]);
        }
        __syncthreads();
    }

#pragma unroll
    for (int mi = 0; mi < 4; mi++)
#pragma unroll
        for (int ni = 0; ni < 4; ni++)
#pragma unroll
            for (int rr = 0; rr < 2; rr++) {
                int row = m0 + wm + mi * 16 + g + rr * 8;
                int b = row & 7, t = row >> 3;
#pragma unroll
                for (int cc = 0; cc < 2; cc++) {
                    int col = n0 + wn + ni * 8 + 2 * tg + cc;
                    int part = col >> 10;
                    int rem = col & 1023;
                    int n = rem >> 6, d = rem & 63;
                    float* dst = (part == 0) ? g_q : (part == 1) ? g_k : g_v;
                    dst[(((size_t)((b << 4) + n) * Tq + t)) * DH + d] = acc[mi][ni][rr * 2 + cc];
                }
            }
}

// ============================================================================
// Fused attention: per (z, 32-row i-tile):
//   S = scale*Q@K^T (causal) -> smem; softmax in smem; probs -> g_S (fp32);
//   attn_vec = P@V -> g_av.  All tf32 MMA.
// Dynamic smem: S[32][1028] f32 | Q[32][68] u32 | K[64][68]/V[64][72] u32
// ============================================================================
#define SS_STRIDE 1028
#define SMEM_S_BYTES (32 * SS_STRIDE * 4)            /* 131584 */
#define SMEM_Q_OFF   SMEM_S_BYTES
#define SMEM_KV_OFF  (SMEM_Q_OFF + 32 * 68 * 4)      /* 140288 */
#define SMEM_TOTAL   (SMEM_KV_OFF + 64 * 72 * 4)     /* 158720 */

__global__ __launch_bounds__(256) void fused_attn() {
    extern __shared__ __align__(16) char smem_raw[];
    float*    Ssm = (float*)smem_raw;                       // [32][1028]
    uint32_t* Qs  = (uint32_t*)(smem_raw + SMEM_Q_OFF);     // [32][68]
    uint32_t* Ks  = (uint32_t*)(smem_raw + SMEM_KV_OFF);    // [64][68]
    uint32_t* Vs  = (uint32_t*)(smem_raw + SMEM_KV_OFF);    // [64][72]

    const int tx = threadIdx.x;
    const int warp = tx >> 5, lane = tx & 31;
    const int g = lane >> 2, tg = lane & 3;
    const int wm = (warp >> 2) * 16;       // 2 warp-rows of 16
    const int wn = (warp & 3) * 16;        // 4 warp-cols of 16

    const int ti = 31 - blockIdx.x;        // heavy tiles first
    const int z = blockIdx.y;
    const int bq = z >> 4, nh = z & 15;
    const int r0 = ti * 32;
    const int jt_n = (ti + 2) >> 1;        // j-tiles of 64 covering [0, r0+32)

    // ---- load Q tile (32 x 64) as tf32 ----
    {
        const int qr = tx >> 3, qc = (tx & 7) * 8;
        const float* qb = g_q + ((size_t)z * Tq + r0) * DH;
        float4 v1 = *(const float4*)(qb + qr * DH + qc);
        float4 v2 = *(const float4*)(qb + qr * DH + qc + 4);
        uint4 u;
        u.x = f2tf(v1.x); u.y = f2tf(v1.y); u.z = f2tf(v1.z); u.w = f2tf(v1.w);
        *(uint4*)&Qs[qr * 68 + qc] = u;
        u.x = f2tf(v2.x); u.y = f2tf(v2.y); u.z = f2tf(v2.z); u.w = f2tf(v2.w);
        *(uint4*)&Qs[qr * 68 + qc + 4] = u;
    }

    const int lr = tx >> 2, lc0 = (tx & 3) << 2;  // K/V tile loaders: 64 rows

    // ==== Phase 1: scores into smem ====
    for (int jt = 0; jt < jt_n; jt++) {
        const float* kb = g_k + ((size_t)z * Tq + jt * 64) * DH;
#pragma unroll
        for (int rr = 0; rr < 4; rr++) {
            int c = lc0 + rr * 16;
            float4 kv = *(const float4*)(kb + lr * DH + c);
            uint4 u;
            u.x = f2tf(kv.x); u.y = f2tf(kv.y); u.z = f2tf(kv.z); u.w = f2tf(kv.w);
            *(uint4*)&Ks[lr * 68 + c] = u;
        }
        __syncthreads();

        float acc[2][4];
#pragma unroll
        for (int ni = 0; ni < 2; ni++)
#pragma unroll
            for (int r = 0; r < 4; r++) acc[ni][r] = 0.f;

#pragma unroll
        for (int ks = 0; ks < 64; ks += 8) {
            uint32_t a0 = Qs[(wm + g) * 68 + ks + tg];
            uint32_t a1 = Qs[(wm + g + 8) * 68 + ks + tg];
            uint32_t a2 = Qs[(wm + g) * 68 + ks + tg + 4];
            uint32_t a3 = Qs[(wm + g + 8) * 68 + ks + tg + 4];
#pragma unroll
            for (int ni = 0; ni < 2; ni++) {
                int c = wn + ni * 8 + g;
                uint32_t b0 = Ks[c * 68 + ks + tg];
                uint32_t b1 = Ks[c * 68 + ks + tg + 4];
                mma8(acc[ni], a0, a1, a2, a3, b0, b1);
            }
        }
        // write scores (masked = -1e30)
#pragma unroll
        for (int ni = 0; ni < 2; ni++)
#pragma unroll
            for (int rr = 0; rr < 2; rr++) {
                int il = wm + g + rr * 8;
#pragma unroll
                for (int cc = 0; cc < 2; cc++) {
                    int jg = jt * 64 + wn + ni * 8 + 2 * tg + cc;
                    Ssm[il * SS_STRIDE + jg] =
                        (jg <= r0 + il) ? acc[ni][rr * 2 + cc] * 0.125f : -1e30f;
                }
            }
        __syncthreads();
    }

    // ==== Phase 2: softmax (4 rows per warp), probs -> g_S + tf32 in smem ====
    {
        const int jmax = jt_n * 64;
#pragma unroll
        for (int rr = 0; rr < 4; rr++) {
            int rl = warp * 4 + rr;
            int i = r0 + rl, len = i + 1;
            float* row = Ssm + rl * SS_STRIDE;

            float m = -1e30f;
            for (int j = lane; j < len; j += 32) m = fmaxf(m, row[j]);
#pragma unroll
            for (int o = 16; o; o >>= 1) m = fmaxf(m, __shfl_xor_sync(0xffffffffu, m, o));

            float s = 0.f;
            for (int j = lane; j < len; j += 32) {
                float e = __expf(row[j] - m);
                row[j] = e;
                s += e;
            }
#pragma unroll
            for (int o = 16; o; o >>= 1) s += __shfl_xor_sync(0xffffffffu, s, o);
            float inv = 1.0f / s;

            float* grow = g_S + ((size_t)z * Tq + i) * Tq;
            for (int j = lane; j < jmax; j += 32) {
                float p = (j < len) ? row[j] * inv : 0.f;
                if (j < len) grow[j] = p;
                row[j] = __uint_as_float(f2tf(p));
            }
        }
    }
    __syncthreads();

    // ==== Phase 3: PV (32 x 64) ====
    float pacc[2][4];
#pragma unroll
    for (int ni = 0; ni < 2; ni++)
#pragma unroll
        for (int r = 0; r < 4; r++) pacc[ni][r] = 0.f;

    for (int jt = 0; jt < jt_n; jt++) {
        const float* vb = g_v + ((size_t)z * Tq + jt * 64) * DH;
#pragma unroll
        for (int rr = 0; rr < 4; rr++) {
            int c = lc0 + rr * 16;
            float4 vv = *(const float4*)(vb + lr * DH + c);
            uint4 u;
            u.x = f2tf(vv.x); u.y = f2tf(vv.y); u.z = f2tf(vv.z); u.w = f2tf(vv.w);
            *(uint4*)&Vs[lr * 72 + c] = u;
        }
        __syncthreads();

#pragma unroll
        for (int ks = 0; ks < 64; ks += 8) {
            int col = jt * 64 + ks + tg;
            uint32_t a0 = __float_as_uint(Ssm[(wm + g) * SS_STRIDE + col]);
            uint32_t a1 = __float_as_uint(Ssm[(wm + g + 8) * SS_STRIDE + col]);
            uint32_t a2 = __float_as_uint(Ssm[(wm + g) * SS_STRIDE + col + 4]);
            uint32_t a3 = __float_as_uint(Ssm[(wm + g + 8) * SS_STRIDE + col + 4]);
#pragma unroll
            for (int ni = 0; ni < 2; ni++) {
                int c = wn + ni * 8 + g;
                uint32_t b0 = Vs[(ks + tg) * 72 + c];
                uint32_t b1 = Vs[(ks + tg + 4) * 72 + c];
                mma8(pacc[ni], a0, a1, a2, a3, b0, b1);
            }
        }
        __syncthreads();
    }

#pragma unroll
    for (int ni = 0; ni < 2; ni++)
#pragma unroll
        for (int rr = 0; rr < 2; rr++) {
            int i = r0 + wm + g + rr * 8;
#pragma unroll
            for (int cc = 0; cc < 2; cc++) {
                int d = wn + ni * 8 + 2 * tg + cc;
                g_av[((size_t)(i * Bq + bq)) * ND + nh * 64 + d] = pacc[ni][rr * 2 + cc];
            }
        }
}

// ============================================================================
// Coverage: out[b][j][i] = mean_n prob[b][n][i][j]. 32x32 smem-transpose tile.
// ============================================================================
__global__ __launch_bounds__(256) void coverage_kernel(float* __restrict__ out_cov) {
    const int b = blockIdx.z;
    const int i0 = blockIdx.y * 32, j0 = blockIdx.x * 32;
    const int tx = threadIdx.x;

    if (j0 >= i0 + 32) {
#pragma unroll
        for (int it = 0; it < 4; it++) {
            int idx = tx + it * 256;
            int jj = idx >> 5, ii = idx & 31;
            out_cov[((size_t)b * Tq + j0 + jj) * Tq + i0 + ii] = 0.f;
        }
        return;
    }

    __shared__ float cs[32][33];
#pragma unroll
    for (int it = 0; it < 4; it++) {
        int idx = tx + it * 256;
        int ii = idx >> 5, jj = idx & 31;
        float s = 0.f;
#pragma unroll
        for (int n = 0; n < 16; n++)
            s += g_S[(((size_t)(b * 16 + n) * Tq + i0 + ii) * Tq) + j0 + jj];
        cs[ii][jj] = s * (1.0f / 16.0f);
    }
    __syncthreads();
#pragma unroll
    for (int it = 0; it < 4; it++) {
        int idx = tx + it * 256;
        int jj = idx >> 5, ii = idx & 31;
        out_cov[((size_t)b * Tq + j0 + jj) * Tq + i0 + ii] = cs[ii][jj];
    }
}

// ============================================================================
// Output projection (tf32 MMA): out[8192,1024] = g_av @ W_o[1024,1024]
// ============================================================================
__global__ __launch_bounds__(256) void out_gemm(const float* __restrict__ Wo,
                                                float* __restrict__ out) {
    __shared__ __align__(16) uint32_t As[128][36];
    __shared__ __align__(16) uint32_t Bs[32][136];
    const int tx = threadIdx.x;
    const int warp = tx >> 5, lane = tx & 31;
    const int g = lane >> 2, tg = lane & 3;
    const int wm = (warp >> 2) * 64;
    const int wn = (warp & 3) * 32;
    const int m0 = blockIdx.y * 128, n0 = blockIdx.x * 128;

    const int la_m = tx >> 3, la_k = (tx & 7) << 2;
    const int lb_k = tx >> 5, lb_n = (tx & 31) << 2;

    float acc[4][4][4];
#pragma unroll
    for (int mi = 0; mi < 4; mi++)
#pragma unroll
        for (int ni = 0; ni < 4; ni++)
#pragma unroll
            for (int r = 0; r < 4; r++) acc[mi][ni][r] = 0.f;

    for (int k0 = 0; k0 < ND; k0 += 32) {
#pragma unroll
        for (int rr = 0; rr < 4; rr++) {
            int m = la_m + rr * 32;
            float4 a = *(const float4*)(g_av + (size_t)(m0 + m) * ND + k0 + la_k);
            uint4 v;
            v.x = f2tf(a.x); v.y = f2tf(a.y); v.z = f2tf(a.z); v.w = f2tf(a.w);
            *(uint4*)&As[m][la_k] = v;
        }
#pragma unroll
        for (int rr = 0; rr < 4; rr++) {
            int kk = lb_k + rr * 8;
            float4 b = *(const float4*)(Wo + (size_t)(k0 + kk) * ND + n0 + lb_n);
            uint4 v;
            v.x = f2tf(b.x); v.y = f2tf(b.y); v.z = f2tf(b.z); v.w = f2tf(b.w);
            *(uint4*)&Bs[kk][lb_n] = v;
        }
        __syncthreads();
#pragma unroll
        for (int ks = 0; ks < 32; ks += 8) {
            uint32_t a[4][4], b[4][2];
#pragma unroll
            for (int mi = 0; mi < 4; mi++) {
                int r = wm + mi * 16 + g;
                a[mi][0] = As[r][ks + tg];
                a[mi][1] = As[r + 8][ks + tg];
                a[mi][2] = As[r][ks + tg + 4];
                a[mi][3] = As[r + 8][ks + tg + 4];
            }
#pragma unroll
            for (int ni = 0; ni < 4; ni++) {
                int c = wn + ni * 8 + g;
                b[ni][0] = Bs[ks + tg][c];
                b[ni][1] = Bs[ks + tg + 4][c];
            }
#pragma unroll
            for (int mi = 0; mi < 4; mi++)
#pragma unroll
                for (int ni = 0; ni < 4; ni++)
                    mma8(acc[mi][ni], a[mi][0], a[mi][1], a[mi][2], a[mi][3],
                         b[ni][0], b[ni][1]);
        }
        __syncthreads();
    }

#pragma unroll
    for (int mi = 0; mi < 4; mi++)
#pragma unroll
        for (int ni = 0; ni < 4; ni++)
#pragma unroll
            for (int rr = 0; rr < 2; rr++) {
                int row = m0 + wm + mi * 16 + g + rr * 8;
#pragma unroll
                for (int cc = 0; cc < 2; cc++) {
                    int col = n0 + wn + ni * 8 + 2 * tg + cc;
                    out[(size_t)row * ND + col] = acc[mi][ni][rr * 2 + cc];
                }
            }
}

// ============================================================================
extern "C" void kernel_launch(void* const* d_in, const int* in_sizes, int n_in,
                              void* d_out, int out_size) {
    const float* inp  = (const float*)d_in[0];
    const float* pe   = (const float*)d_in[1];
    const float* Wqkv = (const float*)d_in[3];
    const float* Wo   = (const float*)d_in[4];

    float* out_attn = (float*)d_out;
    float* out_cov  = out_attn + (size_t)TB * ND;

    cudaFuncSetAttribute(fused_attn, cudaFuncAttributeMaxDynamicSharedMemorySize,
                         SMEM_TOTAL);

    qkv_gemm<<<dim3(N3 / 128, TB / 128), 256>>>(inp, pe, Wqkv);
    fused_attn<<<dim3(32, ZN), 256, SMEM_TOTAL>>>();
    coverage_kernel<<<dim3(Tq / 32, Tq / 32, Bq), 256>>>(out_cov);
    out_gemm<<<dim3(ND / 128, TB / 128), 256>>>(Wo, out_attn);
}

// round 4
// speedup vs baseline: 1.1661x; 1.1661x over previous
#include <cuda_runtime.h>
#include <stdint.h>
#include <math.h>

#define Tq 1024
#define Bq 8
#define Dq 1024
#define NH 16
#define DH 64
#define TB (Tq*Bq)       /* 8192 rows */
#define ND (NH*DH)       /* 1024 */
#define N3 (3*ND)        /* 3072 */
#define ZN (Bq*NH)       /* 128 */

// ---- static scratch (zero-initialized; masked region of g_S never written) ----
__device__ float g_x[(size_t)TB*Dq];        // input + pos_enc
__device__ float g_q[(size_t)ZN*Tq*DH];     // [b][n][t][d]
__device__ float g_k[(size_t)ZN*Tq*DH];
__device__ float g_v[(size_t)ZN*Tq*DH];
__device__ float g_av[(size_t)TB*ND];       // [t*B+b][n*64+d]
__device__ float g_S[(size_t)ZN*Tq*Tq];     // probs, [z][i][j] (masked = 0)

// ---- helpers ----
__device__ __forceinline__ uint32_t f2tf(float x) {
    uint32_t y;
    asm("cvt.rna.tf32.f32 %0, %1;" : "=r"(y) : "f"(x));
    return y;
}
__device__ __forceinline__ void mma8(float c[4],
                                     uint32_t a0, uint32_t a1, uint32_t a2, uint32_t a3,
                                     uint32_t b0, uint32_t b1) {
    asm volatile("mma.sync.aligned.m16n8k8.row.col.f32.tf32.tf32.f32 "
                 "{%0,%1,%2,%3}, {%4,%5,%6,%7}, {%8,%9}, {%0,%1,%2,%3};\n"
                 : "+f"(c[0]), "+f"(c[1]), "+f"(c[2]), "+f"(c[3])
                 : "r"(a0), "r"(a1), "r"(a2), "r"(a3), "r"(b0), "r"(b1));
}
#define CP16(dst_u32, src_ptr) \
    asm volatile("cp.async.cg.shared.global [%0], [%1], 16;\n" :: "r"(dst_u32), "l"(src_ptr))
#define CP_COMMIT() asm volatile("cp.async.commit_group;\n")
#define CP_WAIT(n)  asm volatile("cp.async.wait_group %0;\n" :: "n"(n))

// ============================================================================
// x = input + pos_enc (float4)
// ============================================================================
__global__ __launch_bounds__(256) void add_kernel(const float* __restrict__ a,
                                                  const float* __restrict__ b) {
    size_t i = ((size_t)blockIdx.x * 256 + threadIdx.x) * 4;
    float4 va = *(const float4*)(a + i);
    float4 vb = *(const float4*)(b + i);
    float4 o;
    o.x = va.x + vb.x; o.y = va.y + vb.y; o.z = va.z + vb.z; o.w = va.w + vb.w;
    *(float4*)(g_x + i) = o;
}

// ============================================================================
// Generic tf32 GEMM body: C[ M x 128-tile ] = A[*,K] @ B[K,*], cp.async 2-stage.
// A tile 128x32 fp32 (stride 36), B tile 32x128 fp32 (stride 136), BK=32.
// Conversion to tf32 happens at fragment-consume time (identical values).
// ============================================================================
#define A_STG 4608   /* 128*36 floats per stage */
#define B_STG 4352   /* 32*136 floats per stage */
#define GEMM_SMEM ((2*A_STG + 2*B_STG) * 4)   /* 71680 bytes */

struct GemmFrag { float acc[4][4][4]; };

__device__ __forceinline__ void gemm_issue(float* Af, float* Bf, uint32_t aB, uint32_t bB,
                                           int s, const float* __restrict__ Aglob,
                                           const float* __restrict__ Bglob,
                                           int ldA, int ldB, int m0, int n0, int k0,
                                           int tx) {
    const int a_r = tx >> 3, a_c = (tx & 7) * 4;
    const int b_r = tx >> 5, b_c = (tx & 31) * 4;
#pragma unroll
    for (int p = 0; p < 4; p++) {
        int r = a_r + p * 32;
        uint32_t dst = aB + (uint32_t)(s * A_STG + r * 36 + a_c) * 4u;
        const float* src = Aglob + (size_t)(m0 + r) * ldA + k0 + a_c;
        CP16(dst, src);
    }
#pragma unroll
    for (int p = 0; p < 4; p++) {
        int r = b_r + p * 8;
        uint32_t dst = bB + (uint32_t)(s * B_STG + r * 136 + b_c) * 4u;
        const float* src = Bglob + (size_t)(k0 + r) * ldB + n0 + b_c;
        CP16(dst, src);
    }
}

__device__ __forceinline__ void gemm_compute(GemmFrag& F, const float* Af, const float* Bf,
                                             int s, int wm, int wn, int g, int tg) {
    const float* A = Af + s * A_STG;
    const float* B = Bf + s * B_STG;
#pragma unroll
    for (int ks = 0; ks < 32; ks += 8) {
        uint32_t a[4][4], b[4][2];
#pragma unroll
        for (int mi = 0; mi < 4; mi++) {
            int r = wm + mi * 16 + g;
            a[mi][0] = f2tf(A[r * 36 + ks + tg]);
            a[mi][1] = f2tf(A[(r + 8) * 36 + ks + tg]);
            a[mi][2] = f2tf(A[r * 36 + ks + tg + 4]);
            a[mi][3] = f2tf(A[(r + 8) * 36 + ks + tg + 4]);
        }
#pragma unroll
        for (int ni = 0; ni < 4; ni++) {
            int c = wn + ni * 8 + g;
            b[ni][0] = f2tf(B[(ks + tg) * 136 + c]);
            b[ni][1] = f2tf(B[(ks + tg + 4) * 136 + c]);
        }
#pragma unroll
        for (int mi = 0; mi < 4; mi++)
#pragma unroll
            for (int ni = 0; ni < 4; ni++)
                mma8(F.acc[mi][ni], a[mi][0], a[mi][1], a[mi][2], a[mi][3],
                     b[ni][0], b[ni][1]);
    }
}

// ============================================================================
// QKV GEMM: C[8192,3072] = g_x[8192,1024] @ W[1024,3072], scatter epilogue.
// ============================================================================
__global__ __launch_bounds__(256, 2) void qkv_gemm(const float* __restrict__ W) {
    extern __shared__ float sm[];
    float* Af = sm;
    float* Bf = sm + 2 * A_STG;
    uint32_t aB = (uint32_t)__cvta_generic_to_shared(Af);
    uint32_t bB = (uint32_t)__cvta_generic_to_shared(Bf);
    const int tx = threadIdx.x;
    const int warp = tx >> 5, lane = tx & 31;
    const int g = lane >> 2, tg = lane & 3;
    const int wm = (warp >> 2) * 64, wn = (warp & 3) * 32;
    const int m0 = blockIdx.y * 128, n0 = blockIdx.x * 128;

    GemmFrag F;
#pragma unroll
    for (int mi = 0; mi < 4; mi++)
#pragma unroll
        for (int ni = 0; ni < 4; ni++)
#pragma unroll
            for (int r = 0; r < 4; r++) F.acc[mi][ni][r] = 0.f;

    gemm_issue(Af, Bf, aB, bB, 0, g_x, W, Dq, N3, m0, n0, 0, tx);
    CP_COMMIT();
    int buf = 0;
#pragma unroll 1
    for (int it = 0; it < 32; it++) {
        if (it + 1 < 32) {
            gemm_issue(Af, Bf, aB, bB, buf ^ 1, g_x, W, Dq, N3, m0, n0, (it + 1) * 32, tx);
            CP_COMMIT();
            CP_WAIT(1);
        } else {
            CP_WAIT(0);
        }
        __syncthreads();
        gemm_compute(F, Af, Bf, buf, wm, wn, g, tg);
        __syncthreads();
        buf ^= 1;
    }

#pragma unroll
    for (int mi = 0; mi < 4; mi++)
#pragma unroll
        for (int ni = 0; ni < 4; ni++)
#pragma unroll
            for (int rr = 0; rr < 2; rr++) {
                int row = m0 + wm + mi * 16 + g + rr * 8;
                int b = row & 7, t = row >> 3;
#pragma unroll
                for (int cc = 0; cc < 2; cc++) {
                    int col = n0 + wn + ni * 8 + 2 * tg + cc;
                    int part = col >> 10;
                    int rem = col & 1023;
                    int n = rem >> 6, d = rem & 63;
                    float* dst = (part == 0) ? g_q : (part == 1) ? g_k : g_v;
                    dst[(((size_t)((b << 4) + n) * Tq + t)) * DH + d] = F.acc[mi][ni][rr * 2 + cc];
                }
            }
}

// ============================================================================
// Output projection: out[8192,1024] = g_av @ W_o[1024,1024]
// ============================================================================
__global__ __launch_bounds__(256, 2) void out_gemm(const float* __restrict__ Wo,
                                                   float* __restrict__ out) {
    extern __shared__ float sm[];
    float* Af = sm;
    float* Bf = sm + 2 * A_STG;
    uint32_t aB = (uint32_t)__cvta_generic_to_shared(Af);
    uint32_t bB = (uint32_t)__cvta_generic_to_shared(Bf);
    const int tx = threadIdx.x;
    const int warp = tx >> 5, lane = tx & 31;
    const int g = lane >> 2, tg = lane & 3;
    const int wm = (warp >> 2) * 64, wn = (warp & 3) * 32;
    const int m0 = blockIdx.y * 128, n0 = blockIdx.x * 128;

    GemmFrag F;
#pragma unroll
    for (int mi = 0; mi < 4; mi++)
#pragma unroll
        for (int ni = 0; ni < 4; ni++)
#pragma unroll
            for (int r = 0; r < 4; r++) F.acc[mi][ni][r] = 0.f;

    gemm_issue(Af, Bf, aB, bB, 0, g_av, Wo, ND, ND, m0, n0, 0, tx);
    CP_COMMIT();
    int buf = 0;
#pragma unroll 1
    for (int it = 0; it < 32; it++) {
        if (it + 1 < 32) {
            gemm_issue(Af, Bf, aB, bB, buf ^ 1, g_av, Wo, ND, ND, m0, n0, (it + 1) * 32, tx);
            CP_COMMIT();
            CP_WAIT(1);
        } else {
            CP_WAIT(0);
        }
        __syncthreads();
        gemm_compute(F, Af, Bf, buf, wm, wn, g, tg);
        __syncthreads();
        buf ^= 1;
    }

#pragma unroll
    for (int mi = 0; mi < 4; mi++)
#pragma unroll
        for (int ni = 0; ni < 4; ni++)
#pragma unroll
            for (int rr = 0; rr < 2; rr++) {
                int row = m0 + wm + mi * 16 + g + rr * 8;
#pragma unroll
                for (int cc = 0; cc < 2; cc++) {
                    int col = n0 + wn + ni * 8 + 2 * tg + cc;
                    out[(size_t)row * ND + col] = F.acc[mi][ni][rr * 2 + cc];
                }
            }
}

// ============================================================================
// Scores (tf32 MMA): S[z][i][j] = 0.125*dot64(Q,K), causal tiles only.
// ============================================================================
__global__ __launch_bounds__(256) void score_kernel() {
    const int z = blockIdx.y;
    const int p = blockIdx.x;
    int ti = 0;
    while ((ti + 1) * (ti + 2) / 2 <= p) ti++;
    const int tj = p - ti * (ti + 1) / 2;

    __shared__ __align__(16) uint32_t Qs[64][68];
    __shared__ __align__(16) uint32_t Ks[64][68];
    const int tx = threadIdx.x;
    const int warp = tx >> 5, lane = tx & 31;
    const int g = lane >> 2, tg = lane & 3;
    const int wm = (warp >> 2) * 32;
    const int wn = (warp & 3) * 16;

    const int lr = tx >> 2, lc0 = (tx & 3) << 2;
    const float* qb = g_q + ((size_t)z * Tq + ti * 64) * DH;
    const float* kb = g_k + ((size_t)z * Tq + tj * 64) * DH;
#pragma unroll
    for (int rr = 0; rr < 4; rr++) {
        int c = lc0 + rr * 16;
        float4 qv = *(const float4*)(qb + lr * DH + c);
        uint4 u;
        u.x = f2tf(qv.x); u.y = f2tf(qv.y); u.z = f2tf(qv.z); u.w = f2tf(qv.w);
        *(uint4*)&Qs[lr][c] = u;
        float4 kv = *(const float4*)(kb + lr * DH + c);
        u.x = f2tf(kv.x); u.y = f2tf(kv.y); u.z = f2tf(kv.z); u.w = f2tf(kv.w);
        *(uint4*)&Ks[lr][c] = u;
    }
    __syncthreads();

    float acc[2][2][4];
#pragma unroll
    for (int mi = 0; mi < 2; mi++)
#pragma unroll
        for (int ni = 0; ni < 2; ni++)
#pragma unroll
            for (int r = 0; r < 4; r++) acc[mi][ni][r] = 0.f;

#pragma unroll
    for (int ks = 0; ks < 64; ks += 8) {
        uint32_t a[2][4], b[2][2];
#pragma unroll
        for (int mi = 0; mi < 2; mi++) {
            int r = wm + mi * 16 + g;
            a[mi][0] = Qs[r][ks + tg];
            a[mi][1] = Qs[r + 8][ks + tg];
            a[mi][2] = Qs[r][ks + tg + 4];
            a[mi][3] = Qs[r + 8][ks + tg + 4];
        }
#pragma unroll
        for (int ni = 0; ni < 2; ni++) {
            int c = wn + ni * 8 + g;
            b[ni][0] = Ks[c][ks + tg];
            b[ni][1] = Ks[c][ks + tg + 4];
        }
#pragma unroll
        for (int mi = 0; mi < 2; mi++)
#pragma unroll
            for (int ni = 0; ni < 2; ni++)
                mma8(acc[mi][ni], a[mi][0], a[mi][1], a[mi][2], a[mi][3],
                     b[ni][0], b[ni][1]);
    }

    const float scale = 0.125f;
#pragma unroll
    for (int mi = 0; mi < 2; mi++)
#pragma unroll
        for (int ni = 0; ni < 2; ni++)
#pragma unroll
            for (int rr = 0; rr < 2; rr++) {
                int i = ti * 64 + wm + mi * 16 + g + rr * 8;
#pragma unroll
                for (int cc = 0; cc < 2; cc++) {
                    int j = tj * 64 + wn + ni * 8 + 2 * tg + cc;
                    if (j <= i)
                        g_S[((size_t)z * Tq + i) * Tq + j] = acc[mi][ni][rr * 2 + cc] * scale;
                }
            }
}

// ============================================================================
// Row softmax in place over j in [0, i].
// ============================================================================
__global__ __launch_bounds__(128) void softmax_kernel() {
    const int rid = blockIdx.x;
    const int i = rid & (Tq - 1);
    float* row = g_S + (size_t)rid * Tq;
    const int len = i + 1;
    const int tx = threadIdx.x;

    float vals[8];
    float m = -1e30f;
#pragma unroll
    for (int u = 0; u < 8; u++) {
        int j = tx + u * 128;
        vals[u] = (j < len) ? row[j] : -1e30f;
        m = fmaxf(m, vals[u]);
    }
    __shared__ float redm[4];
    __shared__ float reds[4];
#pragma unroll
    for (int o = 16; o; o >>= 1) m = fmaxf(m, __shfl_xor_sync(0xffffffffu, m, o));
    if ((tx & 31) == 0) redm[tx >> 5] = m;
    __syncthreads();
    m = fmaxf(fmaxf(redm[0], redm[1]), fmaxf(redm[2], redm[3]));

    float s = 0.f;
#pragma unroll
    for (int u = 0; u < 8; u++) {
        int j = tx + u * 128;
        if (j < len) {
            vals[u] = __expf(vals[u] - m);
            s += vals[u];
        }
    }
#pragma unroll
    for (int o = 16; o; o >>= 1) s += __shfl_xor_sync(0xffffffffu, s, o);
    if ((tx & 31) == 0) reds[tx >> 5] = s;
    __syncthreads();
    s = reds[0] + reds[1] + reds[2] + reds[3];

    const float inv = 1.0f / s;
#pragma unroll
    for (int u = 0; u < 8; u++) {
        int j = tx + u * 128;
        if (j < len) row[j] = vals[u] * inv;
    }
}

// ============================================================================
// Coverage: out[b][j][i] = mean_n prob[b][n][i][j].
// ============================================================================
__global__ __launch_bounds__(256) void coverage_kernel(float* __restrict__ out_cov) {
    const int b = blockIdx.z;
    const int i0 = blockIdx.y * 32, j0 = blockIdx.x * 32;
    const int tx = threadIdx.x;

    if (j0 >= i0 + 32) {
#pragma unroll
        for (int it = 0; it < 4; it++) {
            int idx = tx + it * 256;
            int jj = idx >> 5, ii = idx & 31;
            out_cov[((size_t)b * Tq + j0 + jj) * Tq + i0 + ii] = 0.f;
        }
        return;
    }

    __shared__ float cs[32][33];
#pragma unroll
    for (int it = 0; it < 4; it++) {
        int idx = tx + it * 256;
        int ii = idx >> 5, jj = idx & 31;
        float s = 0.f;
#pragma unroll
        for (int n = 0; n < 16; n++)
            s += g_S[(((size_t)(b * 16 + n) * Tq + i0 + ii) * Tq) + j0 + jj];
        cs[ii][jj] = s * (1.0f / 16.0f);
    }
    __syncthreads();
#pragma unroll
    for (int it = 0; it < 4; it++) {
        int idx = tx + it * 256;
        int jj = idx >> 5, ii = idx & 31;
        out_cov[((size_t)b * Tq + j0 + jj) * Tq + i0 + ii] = cs[ii][jj];
    }
}

// ============================================================================
// PV (tf32 MMA): attn_vec = P @ V per (z, 64-row i-tile).
// ============================================================================
__global__ __launch_bounds__(256) void av_kernel() {
    const int ti = blockIdx.x;
    const int z = blockIdx.y;
    const int bq = z >> 4, nh = z & 15;
    __shared__ __align__(16) uint32_t Ps[64][68];
    __shared__ __align__(16) uint32_t Vs[64][72];
    const int tx = threadIdx.x;
    const int warp = tx >> 5, lane = tx & 31;
    const int g = lane >> 2, tg = lane & 3;
    const int wm = (warp >> 2) * 32;
    const int wn = (warp & 3) * 16;
    const int lr = tx >> 2, lc0 = (tx & 3) << 2;

    float acc[2][2][4];
#pragma unroll
    for (int mi = 0; mi < 2; mi++)
#pragma unroll
        for (int ni = 0; ni < 2; ni++)
#pragma unroll
            for (int r = 0; r < 4; r++) acc[mi][ni][r] = 0.f;

    for (int jt = 0; jt <= ti; jt++) {
        const float* pb = g_S + ((size_t)z * Tq + ti * 64) * Tq + jt * 64;
        const float* vb = g_v + ((size_t)z * Tq + jt * 64) * DH;
#pragma unroll
        for (int rr = 0; rr < 4; rr++) {
            int c = lc0 + rr * 16;
            float4 pv = *(const float4*)(pb + (size_t)lr * Tq + c);
            uint4 u;
            u.x = f2tf(pv.x); u.y = f2tf(pv.y); u.z = f2tf(pv.z); u.w = f2tf(pv.w);
            *(uint4*)&Ps[lr][c] = u;
            float4 vv = *(const float4*)(vb + lr * DH + c);
            u.x = f2tf(vv.x); u.y = f2tf(vv.y); u.z = f2tf(vv.z); u.w = f2tf(vv.w);
            *(uint4*)&Vs[lr][c] = u;
        }
        __syncthreads();
#pragma unroll
        for (int ks = 0; ks < 64; ks += 8) {
            uint32_t a[2][4], b[2][2];
#pragma unroll
            for (int mi = 0; mi < 2; mi++) {
                int r = wm + mi * 16 + g;
                a[mi][0] = Ps[r][ks + tg];
                a[mi][1] = Ps[r + 8][ks + tg];
                a[mi][2] = Ps[r][ks + tg + 4];
                a[mi][3] = Ps[r + 8][ks + tg + 4];
            }
#pragma unroll
            for (int ni = 0; ni < 2; ni++) {
                int c = wn + ni * 8 + g;
                b[ni][0] = Vs[ks + tg][c];
                b[ni][1] = Vs[ks + tg + 4][c];
            }
#pragma unroll
            for (int mi = 0; mi < 2; mi++)
#pragma unroll
                for (int ni = 0; ni < 2; ni++)
                    mma8(acc[mi][ni], a[mi][0], a[mi][1], a[mi][2], a[mi][3],
                         b[ni][0], b[ni][1]);
        }
        __syncthreads();
    }

#pragma unroll
    for (int mi = 0; mi < 2; mi++)
#pragma unroll
        for (int ni = 0; ni < 2; ni++)
#pragma unroll
            for (int rr = 0; rr < 2; rr++) {
                int i = ti * 64 + wm + mi * 16 + g + rr * 8;
#pragma unroll
                for (int cc = 0; cc < 2; cc++) {
                    int d = wn + ni * 8 + 2 * tg + cc;
                    g_av[((size_t)(i * Bq + bq)) * ND + nh * 64 + d] = acc[mi][ni][rr * 2 + cc];
                }
            }
}

// ============================================================================
extern "C" void kernel_launch(void* const* d_in, const int* in_sizes, int n_in,
                              void* d_out, int out_size) {
    const float* inp  = (const float*)d_in[0];
    const float* pe   = (const float*)d_in[1];
    const float* Wqkv = (const float*)d_in[3];
    const float* Wo   = (const float*)d_in[4];

    float* out_attn = (float*)d_out;
    float* out_cov  = out_attn + (size_t)TB * ND;

    cudaFuncSetAttribute(qkv_gemm, cudaFuncAttributeMaxDynamicSharedMemorySize, GEMM_SMEM);
    cudaFuncSetAttribute(out_gemm, cudaFuncAttributeMaxDynamicSharedMemorySize, GEMM_SMEM);

    add_kernel<<<TB * Dq / 1024, 256>>>(inp, pe);
    qkv_gemm<<<dim3(N3 / 128, TB / 128), 256, GEMM_SMEM>>>(Wqkv);
    score_kernel<<<dim3(136, ZN), 256>>>();
    softmax_kernel<<<ZN * Tq, 128>>>();
    coverage_kernel<<<dim3(Tq / 32, Tq / 32, Bq), 256>>>(out_cov);
    av_kernel<<<dim3(Tq / 64, ZN), 256>>>();
    out_gemm<<<dim3(ND / 128, TB / 128), 256, GEMM_SMEM>>>(Wo, out_attn);
}

// round 7
// speedup vs baseline: 1.2025x; 1.0312x over previous
#include <cuda_runtime.h>
#include <stdint.h>
#include <math.h>

#define Tq 1024
#define Bq 8
#define Dq 1024
#define NH 16
#define DH 64
#define TB (Tq*Bq)       /* 8192 rows */
#define ND (NH*DH)       /* 1024 */
#define N3 (3*ND)        /* 3072 */
#define ZN (Bq*NH)       /* 128 */

// ---- static scratch (zero-initialized; masked region of g_S never written) ----
__device__ float g_x[(size_t)TB*Dq];        // tf32-rounded input + pos_enc
__device__ float g_wq[(size_t)Dq*N3];       // tf32-rounded W_qkv
__device__ float g_wo[(size_t)ND*ND];       // tf32-rounded W_o
__device__ float g_q[(size_t)ZN*Tq*DH];     // [b][n][t][d]
__device__ float g_k[(size_t)ZN*Tq*DH];
__device__ float g_v[(size_t)ZN*Tq*DH];
__device__ float g_av[(size_t)TB*ND];       // [t*B+b][n*64+d]
__device__ float g_S[(size_t)ZN*Tq*Tq];     // fp32 probs, [z][i][j] (masked = 0)

// ---- helpers ----
__device__ __forceinline__ uint32_t f2tf(float x) {
    uint32_t y;
    asm("cvt.rna.tf32.f32 %0, %1;" : "=r"(y) : "f"(x));
    return y;
}
__device__ __forceinline__ float f2tf_f(float x) { return __uint_as_float(f2tf(x)); }
__device__ __forceinline__ void mma8(float c[4],
                                     uint32_t a0, uint32_t a1, uint32_t a2, uint32_t a3,
                                     uint32_t b0, uint32_t b1) {
    asm volatile("mma.sync.aligned.m16n8k8.row.col.f32.tf32.tf32.f32 "
                 "{%0,%1,%2,%3}, {%4,%5,%6,%7}, {%8,%9}, {%0,%1,%2,%3};\n"
                 : "+f"(c[0]), "+f"(c[1]), "+f"(c[2]), "+f"(c[3])
                 : "r"(a0), "r"(a1), "r"(a2), "r"(a3), "r"(b0), "r"(b1));
}
#define CP16(dst_u32, src_ptr) \
    asm volatile("cp.async.cg.shared.global [%0], [%1], 16;\n" :: "r"(dst_u32), "l"(src_ptr))
#define CP_COMMIT() asm volatile("cp.async.commit_group;\n")
#define CP_WAIT(n)  asm volatile("cp.async.wait_group %0;\n" :: "n"(n))

// ============================================================================
// x = tf32(input + pos_enc)   (g_x referenced from device code only)
// ============================================================================
__global__ __launch_bounds__(256) void add_kernel(const float* __restrict__ a,
                                                  const float* __restrict__ b) {
    size_t i = ((size_t)blockIdx.x * 256 + threadIdx.x) * 4;
    float4 va = *(const float4*)(a + i);
    float4 vb = *(const float4*)(b + i);
    float4 o;
    o.x = f2tf_f(va.x + vb.x); o.y = f2tf_f(va.y + vb.y);
    o.z = f2tf_f(va.z + vb.z); o.w = f2tf_f(va.w + vb.w);
    *(float4*)(g_x + i) = o;
}

// ============================================================================
// tf32-round weights into device-global scratch.
// NOTE: destinations are device symbols referenced from DEVICE code — passing
// them as host-side kernel args was the R5/R6 all-zeros bug.
// ============================================================================
__global__ __launch_bounds__(256) void round_wq(const float* __restrict__ src) {
    size_t i = ((size_t)blockIdx.x * 256 + threadIdx.x) * 4;
    float4 v = *(const float4*)(src + i);
    float4 o;
    o.x = f2tf_f(v.x); o.y = f2tf_f(v.y); o.z = f2tf_f(v.z); o.w = f2tf_f(v.w);
    *(float4*)(g_wq + i) = o;
}
__global__ __launch_bounds__(256) void round_wo(const float* __restrict__ src) {
    size_t i = ((size_t)blockIdx.x * 256 + threadIdx.x) * 4;
    float4 v = *(const float4*)(src + i);
    float4 o;
    o.x = f2tf_f(v.x); o.y = f2tf_f(v.y); o.z = f2tf_f(v.z); o.w = f2tf_f(v.w);
    *(float4*)(g_wo + i) = o;
}

// ============================================================================
// Generic tf32 GEMM body, cp.async 2-stage. Inputs pre-rounded -> no cvt.
// ============================================================================
#define A_STG 4608   /* 128*36 floats per stage */
#define B_STG 4352   /* 32*136 floats per stage */
#define GEMM_SMEM ((2*A_STG + 2*B_STG) * 4)   /* 71680 bytes */

struct GemmFrag { float acc[4][4][4]; };

__device__ __forceinline__ void gemm_issue(uint32_t aB, uint32_t bB,
                                           int s, const float* __restrict__ Aglob,
                                           const float* __restrict__ Bglob,
                                           int ldA, int ldB, int m0, int n0, int k0,
                                           int tx) {
    const int a_r = tx >> 3, a_c = (tx & 7) * 4;
    const int b_r = tx >> 5, b_c = (tx & 31) * 4;
#pragma unroll
    for (int p = 0; p < 4; p++) {
        int r = a_r + p * 32;
        uint32_t dst = aB + (uint32_t)(s * A_STG + r * 36 + a_c) * 4u;
        const float* src = Aglob + (size_t)(m0 + r) * ldA + k0 + a_c;
        CP16(dst, src);
    }
#pragma unroll
    for (int p = 0; p < 4; p++) {
        int r = b_r + p * 8;
        uint32_t dst = bB + (uint32_t)(s * B_STG + r * 136 + b_c) * 4u;
        const float* src = Bglob + (size_t)(k0 + r) * ldB + n0 + b_c;
        CP16(dst, src);
    }
}

__device__ __forceinline__ void gemm_compute(GemmFrag& F, const float* Af, const float* Bf,
                                             int s, int wm, int wn, int g, int tg) {
    const uint32_t* A = (const uint32_t*)(Af + s * A_STG);
    const uint32_t* B = (const uint32_t*)(Bf + s * B_STG);
#pragma unroll
    for (int ks = 0; ks < 32; ks += 8) {
        uint32_t a[4][4], b[4][2];
#pragma unroll
        for (int mi = 0; mi < 4; mi++) {
            int r = wm + mi * 16 + g;
            a[mi][0] = A[r * 36 + ks + tg];
            a[mi][1] = A[(r + 8) * 36 + ks + tg];
            a[mi][2] = A[r * 36 + ks + tg + 4];
            a[mi][3] = A[(r + 8) * 36 + ks + tg + 4];
        }
#pragma unroll
        for (int ni = 0; ni < 4; ni++) {
            int c = wn + ni * 8 + g;
            b[ni][0] = B[(ks + tg) * 136 + c];
            b[ni][1] = B[(ks + tg + 4) * 136 + c];
        }
#pragma unroll
        for (int mi = 0; mi < 4; mi++)
#pragma unroll
            for (int ni = 0; ni < 4; ni++)
                mma8(F.acc[mi][ni], a[mi][0], a[mi][1], a[mi][2], a[mi][3],
                     b[ni][0], b[ni][1]);
    }
}

// ============================================================================
// QKV GEMM: [8192,3072] = g_x @ g_wq, scatter epilogue.
// ============================================================================
__global__ __launch_bounds__(256, 2) void qkv_gemm() {
    extern __shared__ float sm[];
    float* Af = sm;
    float* Bf = sm + 2 * A_STG;
    uint32_t aB = (uint32_t)__cvta_generic_to_shared(Af);
    uint32_t bB = (uint32_t)__cvta_generic_to_shared(Bf);
    const int tx = threadIdx.x;
    const int warp = tx >> 5, lane = tx & 31;
    const int g = lane >> 2, tg = lane & 3;
    const int wm = (warp >> 2) * 64, wn = (warp & 3) * 32;
    const int m0 = blockIdx.y * 128, n0 = blockIdx.x * 128;

    GemmFrag F;
#pragma unroll
    for (int mi = 0; mi < 4; mi++)
#pragma unroll
        for (int ni = 0; ni < 4; ni++)
#pragma unroll
            for (int r = 0; r < 4; r++) F.acc[mi][ni][r] = 0.f;

    gemm_issue(aB, bB, 0, g_x, g_wq, Dq, N3, m0, n0, 0, tx);
    CP_COMMIT();
    int buf = 0;
#pragma unroll 1
    for (int it = 0; it < 32; it++) {
        if (it + 1 < 32) {
            gemm_issue(aB, bB, buf ^ 1, g_x, g_wq, Dq, N3, m0, n0, (it + 1) * 32, tx);
            CP_COMMIT();
            CP_WAIT(1);
        } else {
            CP_WAIT(0);
        }
        __syncthreads();
        gemm_compute(F, Af, Bf, buf, wm, wn, g, tg);
        __syncthreads();
        buf ^= 1;
    }

#pragma unroll
    for (int mi = 0; mi < 4; mi++)
#pragma unroll
        for (int ni = 0; ni < 4; ni++)
#pragma unroll
            for (int rr = 0; rr < 2; rr++) {
                int row = m0 + wm + mi * 16 + g + rr * 8;
                int b = row & 7, t = row >> 3;
#pragma unroll
                for (int cc = 0; cc < 2; cc++) {
                    int col = n0 + wn + ni * 8 + 2 * tg + cc;
                    int part = col >> 10;
                    int rem = col & 1023;
                    int n = rem >> 6, d = rem & 63;
                    float* dst = (part == 0) ? g_q : (part == 1) ? g_k : g_v;
                    dst[(((size_t)((b << 4) + n) * Tq + t)) * DH + d] = F.acc[mi][ni][rr * 2 + cc];
                }
            }
}

// ============================================================================
// Output projection: out[8192,1024] = g_av @ g_wo
// ============================================================================
__global__ __launch_bounds__(256, 2) void out_gemm(float* __restrict__ out) {
    extern __shared__ float sm[];
    float* Af = sm;
    float* Bf = sm + 2 * A_STG;
    uint32_t aB = (uint32_t)__cvta_generic_to_shared(Af);
    uint32_t bB = (uint32_t)__cvta_generic_to_shared(Bf);
    const int tx = threadIdx.x;
    const int warp = tx >> 5, lane = tx & 31;
    const int g = lane >> 2, tg = lane & 3;
    const int wm = (warp >> 2) * 64, wn = (warp & 3) * 32;
    const int m0 = blockIdx.y * 128, n0 = blockIdx.x * 128;

    GemmFrag F;
#pragma unroll
    for (int mi = 0; mi < 4; mi++)
#pragma unroll
        for (int ni = 0; ni < 4; ni++)
#pragma unroll
            for (int r = 0; r < 4; r++) F.acc[mi][ni][r] = 0.f;

    gemm_issue(aB, bB, 0, g_av, g_wo, ND, ND, m0, n0, 0, tx);
    CP_COMMIT();
    int buf = 0;
#pragma unroll 1
    for (int it = 0; it < 32; it++) {
        if (it + 1 < 32) {
            gemm_issue(aB, bB, buf ^ 1, g_av, g_wo, ND, ND, m0, n0, (it + 1) * 32, tx);
            CP_COMMIT();
            CP_WAIT(1);
        } else {
            CP_WAIT(0);
        }
        __syncthreads();
        gemm_compute(F, Af, Bf, buf, wm, wn, g, tg);
        __syncthreads();
        buf ^= 1;
    }

#pragma unroll
    for (int mi = 0; mi < 4; mi++)
#pragma unroll
        for (int ni = 0; ni < 4; ni++)
#pragma unroll
            for (int rr = 0; rr < 2; rr++) {
                int row = m0 + wm + mi * 16 + g + rr * 8;
#pragma unroll
                for (int cc = 0; cc < 2; cc++) {
                    int col = n0 + wn + ni * 8 + 2 * tg + cc;
                    out[(size_t)row * ND + col] = F.acc[mi][ni][rr * 2 + cc];
                }
            }
}

// ============================================================================
// Scores: S[z][i][j] = 0.125*dot64(Q,K), causal tiles only.
// ============================================================================
__global__ __launch_bounds__(256) void score_kernel() {
    const int z = blockIdx.y;
    const int p = blockIdx.x;
    int ti = 0;
    while ((ti + 1) * (ti + 2) / 2 <= p) ti++;
    const int tj = p - ti * (ti + 1) / 2;

    __shared__ __align__(16) uint32_t Qs[64][68];
    __shared__ __align__(16) uint32_t Ks[64][68];
    const int tx = threadIdx.x;
    const int warp = tx >> 5, lane = tx & 31;
    const int g = lane >> 2, tg = lane & 3;
    const int wm = (warp >> 2) * 32;
    const int wn = (warp & 3) * 16;

    const int lr = tx >> 2, lc0 = (tx & 3) << 2;
    const float* qb = g_q + ((size_t)z * Tq + ti * 64) * DH;
    const float* kb = g_k + ((size_t)z * Tq + tj * 64) * DH;
#pragma unroll
    for (int rr = 0; rr < 4; rr++) {
        int c = lc0 + rr * 16;
        float4 qv = *(const float4*)(qb + lr * DH + c);
        uint4 u;
        u.x = f2tf(qv.x); u.y = f2tf(qv.y); u.z = f2tf(qv.z); u.w = f2tf(qv.w);
        *(uint4*)&Qs[lr][c] = u;
        float4 kv = *(const float4*)(kb + lr * DH + c);
        u.x = f2tf(kv.x); u.y = f2tf(kv.y); u.z = f2tf(kv.z); u.w = f2tf(kv.w);
        *(uint4*)&Ks[lr][c] = u;
    }
    __syncthreads();

    float acc[2][2][4];
#pragma unroll
    for (int mi = 0; mi < 2; mi++)
#pragma unroll
        for (int ni = 0; ni < 2; ni++)
#pragma unroll
            for (int r = 0; r < 4; r++) acc[mi][ni][r] = 0.f;

#pragma unroll
    for (int ks = 0; ks < 64; ks += 8) {
        uint32_t a[2][4], b[2][2];
#pragma unroll
        for (int mi = 0; mi < 2; mi++) {
            int r = wm + mi * 16 + g;
            a[mi][0] = Qs[r][ks + tg];
            a[mi][1] = Qs[r + 8][ks + tg];
            a[mi][2] = Qs[r][ks + tg + 4];
            a[mi][3] = Qs[r + 8][ks + tg + 4];
        }
#pragma unroll
        for (int ni = 0; ni < 2; ni++) {
            int c = wn + ni * 8 + g;
            b[ni][0] = Ks[c][ks + tg];
            b[ni][1] = Ks[c][ks + tg + 4];
        }
#pragma unroll
        for (int mi = 0; mi < 2; mi++)
#pragma unroll
            for (int ni = 0; ni < 2; ni++)
                mma8(acc[mi][ni], a[mi][0], a[mi][1], a[mi][2], a[mi][3],
                     b[ni][0], b[ni][1]);
    }

    const float scale = 0.125f;
#pragma unroll
    for (int mi = 0; mi < 2; mi++)
#pragma unroll
        for (int ni = 0; ni < 2; ni++)
#pragma unroll
            for (int rr = 0; rr < 2; rr++) {
                int i = ti * 64 + wm + mi * 16 + g + rr * 8;
#pragma unroll
                for (int cc = 0; cc < 2; cc++) {
                    int j = tj * 64 + wn + ni * 8 + 2 * tg + cc;
                    if (j <= i)
                        g_S[((size_t)z * Tq + i) * Tq + j] = acc[mi][ni][rr * 2 + cc] * scale;
                }
            }
}

// ============================================================================
// Row softmax, vectorized: 128 threads, each owns one 32B segment (8 floats).
// ============================================================================
__global__ __launch_bounds__(128) void softmax_kernel() {
    const int rid = blockIdx.x;
    const int i = rid & (Tq - 1);
    float* row = g_S + (size_t)rid * Tq;
    const int len = i + 1;
    const int tx = threadIdx.x;
    const int j0 = tx * 8;

    float4 v0 = *(const float4*)(row + j0);
    float4 v1 = *(const float4*)(row + j0 + 4);
    float vals[8] = {v0.x, v0.y, v0.z, v0.w, v1.x, v1.y, v1.z, v1.w};

    float m = -1e30f;
#pragma unroll
    for (int u = 0; u < 8; u++)
        if (j0 + u < len) m = fmaxf(m, vals[u]);

    __shared__ float redm[4];
    __shared__ float reds[4];
#pragma unroll
    for (int o = 16; o; o >>= 1) m = fmaxf(m, __shfl_xor_sync(0xffffffffu, m, o));
    if ((tx & 31) == 0) redm[tx >> 5] = m;
    __syncthreads();
    m = fmaxf(fmaxf(redm[0], redm[1]), fmaxf(redm[2], redm[3]));

    float s = 0.f;
#pragma unroll
    for (int u = 0; u < 8; u++) {
        float e = __expf(vals[u] - m);
        vals[u] = e;
        if (j0 + u < len) s += e;
    }
#pragma unroll
    for (int o = 16; o; o >>= 1) s += __shfl_xor_sync(0xffffffffu, s, o);
    if ((tx & 31) == 0) reds[tx >> 5] = s;
    __syncthreads();
    s = reds[0] + reds[1] + reds[2] + reds[3];
    const float inv = 1.0f / s;

    if (j0 + 8 <= len) {
        float4 o0, o1;
        o0.x = vals[0] * inv; o0.y = vals[1] * inv; o0.z = vals[2] * inv; o0.w = vals[3] * inv;
        o1.x = vals[4] * inv; o1.y = vals[5] * inv; o1.z = vals[6] * inv; o1.w = vals[7] * inv;
        *(float4*)(row + j0) = o0;
        *(float4*)(row + j0 + 4) = o1;
    } else {
#pragma unroll
        for (int u = 0; u < 8; u++)
            if (j0 + u < len) row[j0 + u] = vals[u] * inv;
    }
}

// ============================================================================
// Coverage: out[b][j][i] = mean_n prob[b][n][i][j].
// ============================================================================
__global__ __launch_bounds__(256) void coverage_kernel(float* __restrict__ out_cov) {
    const int b = blockIdx.z;
    const int i0 = blockIdx.y * 32, j0 = blockIdx.x * 32;
    const int tx = threadIdx.x;

    if (j0 >= i0 + 32) {
#pragma unroll
        for (int it = 0; it < 4; it++) {
            int idx = tx + it * 256;
            int jj = idx >> 5, ii = idx & 31;
            out_cov[((size_t)b * Tq + j0 + jj) * Tq + i0 + ii] = 0.f;
        }
        return;
    }

    __shared__ float cs[32][33];
#pragma unroll
    for (int it = 0; it < 4; it++) {
        int idx = tx + it * 256;
        int ii = idx >> 5, jj = idx & 31;
        float s = 0.f;
#pragma unroll
        for (int n = 0; n < 16; n++)
            s += g_S[(((size_t)(b * 16 + n) * Tq + i0 + ii) * Tq) + j0 + jj];
        cs[ii][jj] = s * (1.0f / 16.0f);
    }
    __syncthreads();
#pragma unroll
    for (int it = 0; it < 4; it++) {
        int idx = tx + it * 256;
        int jj = idx >> 5, ii = idx & 31;
        out_cov[((size_t)b * Tq + j0 + jj) * Tq + i0 + ii] = cs[ii][jj];
    }
}

// ============================================================================
// PV (tf32 MMA): attn_vec = P @ V per (z, 64-row i-tile).
// ============================================================================
__global__ __launch_bounds__(256) void av_kernel() {
    const int ti = blockIdx.x;
    const int z = blockIdx.y;
    const int bq = z >> 4, nh = z & 15;
    __shared__ __align__(16) uint32_t Ps[64][68];
    __shared__ __align__(16) uint32_t Vs[64][72];
    const int tx = threadIdx.x;
    const int warp = tx >> 5, lane = tx & 31;
    const int g = lane >> 2, tg = lane & 3;
    const int wm = (warp >> 2) * 32;
    const int wn = (warp & 3) * 16;
    const int lr = tx >> 2, lc0 = (tx & 3) << 2;

    float acc[2][2][4];
#pragma unroll
    for (int mi = 0; mi < 2; mi++)
#pragma unroll
        for (int ni = 0; ni < 2; ni++)
#pragma unroll
            for (int r = 0; r < 4; r++) acc[mi][ni][r] = 0.f;

    for (int jt = 0; jt <= ti; jt++) {
        const float* pb = g_S + ((size_t)z * Tq + ti * 64) * Tq + jt * 64;
        const float* vb = g_v + ((size_t)z * Tq + jt * 64) * DH;
#pragma unroll
        for (int rr = 0; rr < 4; rr++) {
            int c = lc0 + rr * 16;
            float4 pv = *(const float4*)(pb + (size_t)lr * Tq + c);
            uint4 u;
            u.x = f2tf(pv.x); u.y = f2tf(pv.y); u.z = f2tf(pv.z); u.w = f2tf(pv.w);
            *(uint4*)&Ps[lr][c] = u;
            float4 vv = *(const float4*)(vb + lr * DH + c);
            u.x = f2tf(vv.x); u.y = f2tf(vv.y); u.z = f2tf(vv.z); u.w = f2tf(vv.w);
            *(uint4*)&Vs[lr][c] = u;
        }
        __syncthreads();
#pragma unroll
        for (int ks = 0; ks < 64; ks += 8) {
            uint32_t a[2][4], b[2][2];
#pragma unroll
            for (int mi = 0; mi < 2; mi++) {
                int r = wm + mi * 16 + g;
                a[mi][0] = Ps[r][ks + tg];
                a[mi][1] = Ps[r + 8][ks + tg];
                a[mi][2] = Ps[r][ks + tg + 4];
                a[mi][3] = Ps[r + 8][ks + tg + 4];
            }
#pragma unroll
            for (int ni = 0; ni < 2; ni++) {
                int c = wn + ni * 8 + g;
                b[ni][0] = Vs[ks + tg][c];
                b[ni][1] = Vs[ks + tg + 4][c];
            }
#pragma unroll
            for (int mi = 0; mi < 2; mi++)
#pragma unroll
                for (int ni = 0; ni < 2; ni++)
                    mma8(acc[mi][ni], a[mi][0], a[mi][1], a[mi][2], a[mi][3],
                         b[ni][0], b[ni][1]);
        }
        __syncthreads();
    }

#pragma unroll
    for (int mi = 0; mi < 2; mi++)
#pragma unroll
        for (int ni = 0; ni < 2; ni++)
#pragma unroll
            for (int rr = 0; rr < 2; rr++) {
                int i = ti * 64 + wm + mi * 16 + g + rr * 8;
#pragma unroll
                for (int cc = 0; cc < 2; cc++) {
                    int d = wn + ni * 8 + 2 * tg + cc;
                    g_av[((size_t)(i * Bq + bq)) * ND + nh * 64 + d] = acc[mi][ni][rr * 2 + cc];
                }
            }
}

// ============================================================================
extern "C" void kernel_launch(void* const* d_in, const int* in_sizes, int n_in,
                              void* d_out, int out_size) {
    const float* inp  = (const float*)d_in[0];
    const float* pe   = (const float*)d_in[1];
    const float* Wqkv = (const float*)d_in[3];
    const float* Wo   = (const float*)d_in[4];

    float* out_attn = (float*)d_out;
    float* out_cov  = out_attn + (size_t)TB * ND;

    cudaFuncSetAttribute(qkv_gemm, cudaFuncAttributeMaxDynamicSharedMemorySize, GEMM_SMEM);
    cudaFuncSetAttribute(out_gemm, cudaFuncAttributeMaxDynamicSharedMemorySize, GEMM_SMEM);

    add_kernel<<<TB * Dq / 1024, 256>>>(inp, pe);
    round_wq<<<Dq * N3 / 1024, 256>>>(Wqkv);
    round_wo<<<ND * ND / 1024, 256>>>(Wo);
    qkv_gemm<<<dim3(N3 / 128, TB / 128), 256, GEMM_SMEM>>>();
    score_kernel<<<dim3(136, ZN), 256>>>();
    softmax_kernel<<<ZN * Tq, 128>>>();
    coverage_kernel<<<dim3(Tq / 32, Tq / 32, Bq), 256>>>(out_cov);
    av_kernel<<<dim3(Tq / 64, ZN), 256>>>();
    out_gemm<<<dim3(ND / 128, TB / 128), 256, GEMM_SMEM>>>(out_attn);
}

// round 8
// speedup vs baseline: 1.2076x; 1.0042x over previous
#include <cuda_runtime.h>
#include <stdint.h>
#include <math.h>

#define Tq 1024
#define Bq 8
#define Dq 1024
#define NH 16
#define DH 64
#define TB (Tq*Bq)       /* 8192 rows */
#define ND (NH*DH)       /* 1024 */
#define N3 (3*ND)        /* 3072 */
#define ZN (Bq*NH)       /* 128 */

// ---- static scratch (zero-initialized; masked region of g_S never written) ----
__device__ float g_x[(size_t)TB*Dq];        // tf32-rounded input + pos_enc
__device__ float g_wq[(size_t)Dq*N3];       // tf32-rounded W_qkv
__device__ float g_wo[(size_t)ND*ND];       // tf32-rounded W_o
__device__ float g_q[(size_t)ZN*Tq*DH];     // [b][n][t][d]
__device__ float g_k[(size_t)ZN*Tq*DH];
__device__ float g_v[(size_t)ZN*Tq*DH];
__device__ float g_av[(size_t)TB*ND];       // [t*B+b][n*64+d]
__device__ float g_S[(size_t)ZN*Tq*Tq];     // fp32 probs, [z][i][j] (masked = 0)

// ---- helpers ----
__device__ __forceinline__ uint32_t f2tf(float x) {
    uint32_t y;
    asm("cvt.rna.tf32.f32 %0, %1;" : "=r"(y) : "f"(x));
    return y;
}
__device__ __forceinline__ float f2tf_f(float x) { return __uint_as_float(f2tf(x)); }
__device__ __forceinline__ void mma8(float c[4],
                                     uint32_t a0, uint32_t a1, uint32_t a2, uint32_t a3,
                                     uint32_t b0, uint32_t b1) {
    asm volatile("mma.sync.aligned.m16n8k8.row.col.f32.tf32.tf32.f32 "
                 "{%0,%1,%2,%3}, {%4,%5,%6,%7}, {%8,%9}, {%0,%1,%2,%3};\n"
                 : "+f"(c[0]), "+f"(c[1]), "+f"(c[2]), "+f"(c[3])
                 : "r"(a0), "r"(a1), "r"(a2), "r"(a3), "r"(b0), "r"(b1));
}
#define CP16(dst_u32, src_ptr) \
    asm volatile("cp.async.cg.shared.global [%0], [%1], 16;\n" :: "r"(dst_u32), "l"(src_ptr))
#define CP_COMMIT() asm volatile("cp.async.commit_group;\n")
#define CP_WAIT(n)  asm volatile("cp.async.wait_group %0;\n" :: "n"(n))

// ============================================================================
// x = tf32(input + pos_enc)
// ============================================================================
__global__ __launch_bounds__(256) void add_kernel(const float* __restrict__ a,
                                                  const float* __restrict__ b) {
    size_t i = ((size_t)blockIdx.x * 256 + threadIdx.x) * 4;
    float4 va = *(const float4*)(a + i);
    float4 vb = *(const float4*)(b + i);
    float4 o;
    o.x = f2tf_f(va.x + vb.x); o.y = f2tf_f(va.y + vb.y);
    o.z = f2tf_f(va.z + vb.z); o.w = f2tf_f(va.w + vb.w);
    *(float4*)(g_x + i) = o;
}

// ============================================================================
// tf32-round weights into device-global scratch (device-code symbol refs only).
// ============================================================================
__global__ __launch_bounds__(256) void round_wq(const float* __restrict__ src) {
    size_t i = ((size_t)blockIdx.x * 256 + threadIdx.x) * 4;
    float4 v = *(const float4*)(src + i);
    float4 o;
    o.x = f2tf_f(v.x); o.y = f2tf_f(v.y); o.z = f2tf_f(v.z); o.w = f2tf_f(v.w);
    *(float4*)(g_wq + i) = o;
}
__global__ __launch_bounds__(256) void round_wo(const float* __restrict__ src) {
    size_t i = ((size_t)blockIdx.x * 256 + threadIdx.x) * 4;
    float4 v = *(const float4*)(src + i);
    float4 o;
    o.x = f2tf_f(v.x); o.y = f2tf_f(v.y); o.z = f2tf_f(v.z); o.w = f2tf_f(v.w);
    *(float4*)(g_wo + i) = o;
}

// ============================================================================
// tf32 GEMM body, cp.async 3-stage, ONE sync per k-iteration.
// Safety: at iter it, issue targets (it+2)%3; the sync this iteration already
// guaranteed all warps finished computing (it-1)%3 == (it+2)%3.
// ============================================================================
#define A_STG 4608   /* 128*36 floats per stage */
#define B_STG 4352   /* 32*136 floats per stage */
#define NSTG  3
#define GEMM_SMEM (NSTG*(A_STG + B_STG) * 4)   /* 107520 bytes */

struct GemmFrag { float acc[4][4][4]; };

__device__ __forceinline__ void gemm_issue(uint32_t aB, uint32_t bB,
                                           int s, const float* __restrict__ Aglob,
                                           const float* __restrict__ Bglob,
                                           int ldA, int ldB, int m0, int n0, int k0,
                                           int tx) {
    const int a_r = tx >> 3, a_c = (tx & 7) * 4;
    const int b_r = tx >> 5, b_c = (tx & 31) * 4;
#pragma unroll
    for (int p = 0; p < 4; p++) {
        int r = a_r + p * 32;
        uint32_t dst = aB + (uint32_t)(s * A_STG + r * 36 + a_c) * 4u;
        const float* src = Aglob + (size_t)(m0 + r) * ldA + k0 + a_c;
        CP16(dst, src);
    }
#pragma unroll
    for (int p = 0; p < 4; p++) {
        int r = b_r + p * 8;
        uint32_t dst = bB + (uint32_t)(s * B_STG + r * 136 + b_c) * 4u;
        const float* src = Bglob + (size_t)(k0 + r) * ldB + n0 + b_c;
        CP16(dst, src);
    }
}

__device__ __forceinline__ void gemm_compute(GemmFrag& F, const float* Af, const float* Bf,
                                             int s, int wm, int wn, int g, int tg) {
    const uint32_t* A = (const uint32_t*)(Af + s * A_STG);
    const uint32_t* B = (const uint32_t*)(Bf + s * B_STG);
#pragma unroll
    for (int ks = 0; ks < 32; ks += 8) {
        uint32_t a[4][4], b[4][2];
#pragma unroll
        for (int mi = 0; mi < 4; mi++) {
            int r = wm + mi * 16 + g;
            a[mi][0] = A[r * 36 + ks + tg];
            a[mi][1] = A[(r + 8) * 36 + ks + tg];
            a[mi][2] = A[r * 36 + ks + tg + 4];
            a[mi][3] = A[(r + 8) * 36 + ks + tg + 4];
        }
#pragma unroll
        for (int ni = 0; ni < 4; ni++) {
            int c = wn + ni * 8 + g;
            b[ni][0] = B[(ks + tg) * 136 + c];
            b[ni][1] = B[(ks + tg + 4) * 136 + c];
        }
#pragma unroll
        for (int mi = 0; mi < 4; mi++)
#pragma unroll
            for (int ni = 0; ni < 4; ni++)
                mma8(F.acc[mi][ni], a[mi][0], a[mi][1], a[mi][2], a[mi][3],
                     b[ni][0], b[ni][1]);
    }
}

#define GEMM_MAINLOOP(Aglob, Bglob, ldA, ldB)                                   \
    gemm_issue(aB, bB, 0, Aglob, Bglob, ldA, ldB, m0, n0, 0, tx);               \
    CP_COMMIT();                                                                \
    gemm_issue(aB, bB, 1, Aglob, Bglob, ldA, ldB, m0, n0, 32, tx);              \
    CP_COMMIT();                                                                \
    _Pragma("unroll 1")                                                         \
    for (int it = 0; it < 32; it++) {                                           \
        if (it == 31) { CP_WAIT(0); } else { CP_WAIT(1); }                      \
        __syncthreads();                                                        \
        if (it + 2 < 32) {                                                      \
            gemm_issue(aB, bB, (it + 2) % NSTG, Aglob, Bglob, ldA, ldB,         \
                       m0, n0, (it + 2) * 32, tx);                              \
            CP_COMMIT();                                                        \
        }                                                                       \
        gemm_compute(F, Af, Bf, it % NSTG, wm, wn, g, tg);                      \
    }

// ============================================================================
// QKV GEMM: [8192,3072] = g_x @ g_wq, scatter epilogue.
// ============================================================================
__global__ __launch_bounds__(256, 2) void qkv_gemm() {
    extern __shared__ float sm[];
    float* Af = sm;
    float* Bf = sm + NSTG * A_STG;
    uint32_t aB = (uint32_t)__cvta_generic_to_shared(Af);
    uint32_t bB = (uint32_t)__cvta_generic_to_shared(Bf);
    const int tx = threadIdx.x;
    const int warp = tx >> 5, lane = tx & 31;
    const int g = lane >> 2, tg = lane & 3;
    const int wm = (warp >> 2) * 64, wn = (warp & 3) * 32;
    const int m0 = blockIdx.y * 128, n0 = blockIdx.x * 128;

    GemmFrag F;
#pragma unroll
    for (int mi = 0; mi < 4; mi++)
#pragma unroll
        for (int ni = 0; ni < 4; ni++)
#pragma unroll
            for (int r = 0; r < 4; r++) F.acc[mi][ni][r] = 0.f;

    GEMM_MAINLOOP(g_x, g_wq, Dq, N3)

#pragma unroll
    for (int mi = 0; mi < 4; mi++)
#pragma unroll
        for (int ni = 0; ni < 4; ni++)
#pragma unroll
            for (int rr = 0; rr < 2; rr++) {
                int row = m0 + wm + mi * 16 + g + rr * 8;
                int b = row & 7, t = row >> 3;
#pragma unroll
                for (int cc = 0; cc < 2; cc++) {
                    int col = n0 + wn + ni * 8 + 2 * tg + cc;
                    int part = col >> 10;
                    int rem = col & 1023;
                    int n = rem >> 6, d = rem & 63;
                    float* dst = (part == 0) ? g_q : (part == 1) ? g_k : g_v;
                    dst[(((size_t)((b << 4) + n) * Tq + t)) * DH + d] = F.acc[mi][ni][rr * 2 + cc];
                }
            }
}

// ============================================================================
// Output projection: out[8192,1024] = g_av @ g_wo
// ============================================================================
__global__ __launch_bounds__(256, 2) void out_gemm(float* __restrict__ out) {
    extern __shared__ float sm[];
    float* Af = sm;
    float* Bf = sm + NSTG * A_STG;
    uint32_t aB = (uint32_t)__cvta_generic_to_shared(Af);
    uint32_t bB = (uint32_t)__cvta_generic_to_shared(Bf);
    const int tx = threadIdx.x;
    const int warp = tx >> 5, lane = tx & 31;
    const int g = lane >> 2, tg = lane & 3;
    const int wm = (warp >> 2) * 64, wn = (warp & 3) * 32;
    const int m0 = blockIdx.y * 128, n0 = blockIdx.x * 128;

    GemmFrag F;
#pragma unroll
    for (int mi = 0; mi < 4; mi++)
#pragma unroll
        for (int ni = 0; ni < 4; ni++)
#pragma unroll
            for (int r = 0; r < 4; r++) F.acc[mi][ni][r] = 0.f;

    GEMM_MAINLOOP(g_av, g_wo, ND, ND)

#pragma unroll
    for (int mi = 0; mi < 4; mi++)
#pragma unroll
        for (int ni = 0; ni < 4; ni++)
#pragma unroll
            for (int rr = 0; rr < 2; rr++) {
                int row = m0 + wm + mi * 16 + g + rr * 8;
#pragma unroll
                for (int cc = 0; cc < 2; cc++) {
                    int col = n0 + wn + ni * 8 + 2 * tg + cc;
                    out[(size_t)row * ND + col] = F.acc[mi][ni][rr * 2 + cc];
                }
            }
}

// ============================================================================
// Scores: S[z][i][j] = 0.125*dot64(Q,K), causal tiles only. (R7-identical.)
// ============================================================================
__global__ __launch_bounds__(256) void score_kernel() {
    const int z = blockIdx.y;
    const int p = blockIdx.x;
    int ti = 0;
    while ((ti + 1) * (ti + 2) / 2 <= p) ti++;
    const int tj = p - ti * (ti + 1) / 2;

    __shared__ __align__(16) uint32_t Qs[64][68];
    __shared__ __align__(16) uint32_t Ks[64][68];
    const int tx = threadIdx.x;
    const int warp = tx >> 5, lane = tx & 31;
    const int g = lane >> 2, tg = lane & 3;
    const int wm = (warp >> 2) * 32;
    const int wn = (warp & 3) * 16;

    const int lr = tx >> 2, lc0 = (tx & 3) << 2;
    const float* qb = g_q + ((size_t)z * Tq + ti * 64) * DH;
    const float* kb = g_k + ((size_t)z * Tq + tj * 64) * DH;
#pragma unroll
    for (int rr = 0; rr < 4; rr++) {
        int c = lc0 + rr * 16;
        float4 qv = *(const float4*)(qb + lr * DH + c);
        uint4 u;
        u.x = f2tf(qv.x); u.y = f2tf(qv.y); u.z = f2tf(qv.z); u.w = f2tf(qv.w);
        *(uint4*)&Qs[lr][c] = u;
        float4 kv = *(const float4*)(kb + lr * DH + c);
        u.x = f2tf(kv.x); u.y = f2tf(kv.y); u.z = f2tf(kv.z); u.w = f2tf(kv.w);
        *(uint4*)&Ks[lr][c] = u;
    }
    __syncthreads();

    float acc[2][2][4];
#pragma unroll
    for (int mi = 0; mi < 2; mi++)
#pragma unroll
        for (int ni = 0; ni < 2; ni++)
#pragma unroll
            for (int r = 0; r < 4; r++) acc[mi][ni][r] = 0.f;

#pragma unroll
    for (int ks = 0; ks < 64; ks += 8) {
        uint32_t a[2][4], b[2][2];
#pragma unroll
        for (int mi = 0; mi < 2; mi++) {
            int r = wm + mi * 16 + g;
            a[mi][0] = Qs[r][ks + tg];
            a[mi][1] = Qs[r + 8][ks + tg];
            a[mi][2] = Qs[r][ks + tg + 4];
            a[mi][3] = Qs[r + 8][ks + tg + 4];
        }
#pragma unroll
        for (int ni = 0; ni < 2; ni++) {
            int c = wn + ni * 8 + g;
            b[ni][0] = Ks[c][ks + tg];
            b[ni][1] = Ks[c][ks + tg + 4];
        }
#pragma unroll
        for (int mi = 0; mi < 2; mi++)
#pragma unroll
            for (int ni = 0; ni < 2; ni++)
                mma8(acc[mi][ni], a[mi][0], a[mi][1], a[mi][2], a[mi][3],
                     b[ni][0], b[ni][1]);
    }

    const float scale = 0.125f;
#pragma unroll
    for (int mi = 0; mi < 2; mi++)
#pragma unroll
        for (int ni = 0; ni < 2; ni++)
#pragma unroll
            for (int rr = 0; rr < 2; rr++) {
                int i = ti * 64 + wm + mi * 16 + g + rr * 8;
#pragma unroll
                for (int cc = 0; cc < 2; cc++) {
                    int j = tj * 64 + wn + ni * 8 + 2 * tg + cc;
                    if (j <= i)
                        g_S[((size_t)z * Tq + i) * Tq + j] = acc[mi][ni][rr * 2 + cc] * scale;
                }
            }
}

// ============================================================================
// Row softmax, vectorized. (R7-identical.)
// ============================================================================
__global__ __launch_bounds__(128) void softmax_kernel() {
    const int rid = blockIdx.x;
    const int i = rid & (Tq - 1);
    float* row = g_S + (size_t)rid * Tq;
    const int len = i + 1;
    const int tx = threadIdx.x;
    const int j0 = tx * 8;

    float4 v0 = *(const float4*)(row + j0);
    float4 v1 = *(const float4*)(row + j0 + 4);
    float vals[8] = {v0.x, v0.y, v0.z, v0.w, v1.x, v1.y, v1.z, v1.w};

    float m = -1e30f;
#pragma unroll
    for (int u = 0; u < 8; u++)
        if (j0 + u < len) m = fmaxf(m, vals[u]);

    __shared__ float redm[4];
    __shared__ float reds[4];
#pragma unroll
    for (int o = 16; o; o >>= 1) m = fmaxf(m, __shfl_xor_sync(0xffffffffu, m, o));
    if ((tx & 31) == 0) redm[tx >> 5] = m;
    __syncthreads();
    m = fmaxf(fmaxf(redm[0], redm[1]), fmaxf(redm[2], redm[3]));

    float s = 0.f;
#pragma unroll
    for (int u = 0; u < 8; u++) {
        float e = __expf(vals[u] - m);
        vals[u] = e;
        if (j0 + u < len) s += e;
    }
#pragma unroll
    for (int o = 16; o; o >>= 1) s += __shfl_xor_sync(0xffffffffu, s, o);
    if ((tx & 31) == 0) reds[tx >> 5] = s;
    __syncthreads();
    s = reds[0] + reds[1] + reds[2] + reds[3];
    const float inv = 1.0f / s;

    if (j0 + 8 <= len) {
        float4 o0, o1;
        o0.x = vals[0] * inv; o0.y = vals[1] * inv; o0.z = vals[2] * inv; o0.w = vals[3] * inv;
        o1.x = vals[4] * inv; o1.y = vals[5] * inv; o1.z = vals[6] * inv; o1.w = vals[7] * inv;
        *(float4*)(row + j0) = o0;
        *(float4*)(row + j0 + 4) = o1;
    } else {
#pragma unroll
        for (int u = 0; u < 8; u++)
            if (j0 + u < len) row[j0 + u] = vals[u] * inv;
    }
}

// ============================================================================
// Coverage: out[b][j][i] = mean_n prob[b][n][i][j]. (R7-identical.)
// ============================================================================
__global__ __launch_bounds__(256) void coverage_kernel(float* __restrict__ out_cov) {
    const int b = blockIdx.z;
    const int i0 = blockIdx.y * 32, j0 = blockIdx.x * 32;
    const int tx = threadIdx.x;

    if (j0 >= i0 + 32) {
#pragma unroll
        for (int it = 0; it < 4; it++) {
            int idx = tx + it * 256;
            int jj = idx >> 5, ii = idx & 31;
            out_cov[((size_t)b * Tq + j0 + jj) * Tq + i0 + ii] = 0.f;
        }
        return;
    }

    __shared__ float cs[32][33];
#pragma unroll
    for (int it = 0; it < 4; it++) {
        int idx = tx + it * 256;
        int ii = idx >> 5, jj = idx & 31;
        float s = 0.f;
#pragma unroll
        for (int n = 0; n < 16; n++)
            s += g_S[(((size_t)(b * 16 + n) * Tq + i0 + ii) * Tq) + j0 + jj];
        cs[ii][jj] = s * (1.0f / 16.0f);
    }
    __syncthreads();
#pragma unroll
    for (int it = 0; it < 4; it++) {
        int idx = tx + it * 256;
        int jj = idx >> 5, ii = idx & 31;
        out_cov[((size_t)b * Tq + j0 + jj) * Tq + i0 + ii] = cs[ii][jj];
    }
}

// ============================================================================
// PV: attn_vec = P @ V per (z, 64-row i-tile), cp.async 2-stage.
// P and V fragments f2tf'd at consume (both stored unrounded in gmem) ->
// numerics identical to R7's av_kernel.
// ============================================================================
#define AVP 4352   /* 64*68 floats per stage */
#define AVV 4608   /* 64*72 floats per stage */
#define AV_SMEM ((2*AVP + 2*AVV) * 4)   /* 71680 bytes */

__global__ __launch_bounds__(256, 2) void av_kernel() {
    extern __shared__ float sm[];
    float* Pf = sm;
    float* Vf = sm + 2 * AVP;
    uint32_t pB = (uint32_t)__cvta_generic_to_shared(Pf);
    uint32_t vB = (uint32_t)__cvta_generic_to_shared(Vf);

    const int ti = (Tq / 64 - 1) - blockIdx.x;   // heavy tiles first
    const int z = blockIdx.y;
    const int bq = z >> 4, nh = z & 15;
    const int tx = threadIdx.x;
    const int warp = tx >> 5, lane = tx & 31;
    const int g = lane >> 2, tg = lane & 3;
    const int wm = (warp >> 2) * 32;
    const int wn = (warp & 3) * 16;

    const int lrow = tx >> 2, lcol = (tx & 3) * 16;
    const float* pbase = g_S + ((size_t)z * Tq + ti * 64 + lrow) * Tq + lcol;
    const float* vbase = g_v + ((size_t)z * Tq + lrow) * DH + lcol;

    const int nj = ti + 1;

    float acc[2][2][4];
#pragma unroll
    for (int mi = 0; mi < 2; mi++)
#pragma unroll
        for (int ni = 0; ni < 2; ni++)
#pragma unroll
            for (int r = 0; r < 4; r++) acc[mi][ni][r] = 0.f;

    // prologue: stage 0 <- j-tile 0
#pragma unroll
    for (int q = 0; q < 4; q++) {
        CP16(pB + (uint32_t)(lrow * 68 + lcol + q * 4) * 4u, pbase + q * 4);
        CP16(vB + (uint32_t)(lrow * 72 + lcol + q * 4) * 4u, vbase + q * 4);
    }
    CP_COMMIT();

    int buf = 0;
#pragma unroll 1
    for (int jt = 0; jt < nj; jt++) {
        if (jt + 1 < nj) {
            int s = buf ^ 1;
            int jn = jt + 1;
#pragma unroll
            for (int q = 0; q < 4; q++) {
                CP16(pB + (uint32_t)(s * AVP + lrow * 68 + lcol + q * 4) * 4u,
                     pbase + jn * 64 + q * 4);
                CP16(vB + (uint32_t)(s * AVV + lrow * 72 + lcol + q * 4) * 4u,
                     vbase + (size_t)jn * 64 * DH + q * 4);
            }
            CP_COMMIT();
            CP_WAIT(1);
        } else {
            CP_WAIT(0);
        }
        __syncthreads();

        const float* P = Pf + buf * AVP;
        const float* V = Vf + buf * AVV;
#pragma unroll
        for (int ks = 0; ks < 64; ks += 8) {
            uint32_t a[2][4], b[2][2];
#pragma unroll
            for (int mi = 0; mi < 2; mi++) {
                int r = wm + mi * 16 + g;
                a[mi][0] = f2tf(P[r * 68 + ks + tg]);
                a[mi][1] = f2tf(P[(r + 8) * 68 + ks + tg]);
                a[mi][2] = f2tf(P[r * 68 + ks + tg + 4]);
                a[mi][3] = f2tf(P[(r + 8) * 68 + ks + tg + 4]);
            }
#pragma unroll
            for (int ni = 0; ni < 2; ni++) {
                int c = wn + ni * 8 + g;
                b[ni][0] = f2tf(V[(ks + tg) * 72 + c]);
                b[ni][1] = f2tf(V[(ks + tg + 4) * 72 + c]);
            }
#pragma unroll
            for (int mi = 0; mi < 2; mi++)
#pragma unroll
                for (int ni = 0; ni < 2; ni++)
                    mma8(acc[mi][ni], a[mi][0], a[mi][1], a[mi][2], a[mi][3],
                         b[ni][0], b[ni][1]);
        }
        __syncthreads();
        buf ^= 1;
    }

#pragma unroll
    for (int mi = 0; mi < 2; mi++)
#pragma unroll
        for (int ni = 0; ni < 2; ni++)
#pragma unroll
            for (int rr = 0; rr < 2; rr++) {
                int i = ti * 64 + wm + mi * 16 + g + rr * 8;
#pragma unroll
                for (int cc = 0; cc < 2; cc++) {
                    int d = wn + ni * 8 + 2 * tg + cc;
                    g_av[((size_t)(i * Bq + bq)) * ND + nh * 64 + d] = acc[mi][ni][rr * 2 + cc];
                }
            }
}

// ============================================================================
extern "C" void kernel_launch(void* const* d_in, const int* in_sizes, int n_in,
                              void* d_out, int out_size) {
    const float* inp  = (const float*)d_in[0];
    const float* pe   = (const float*)d_in[1];
    const float* Wqkv = (const float*)d_in[3];
    const float* Wo   = (const float*)d_in[4];

    float* out_attn = (float*)d_out;
    float* out_cov  = out_attn + (size_t)TB * ND;

    cudaFuncSetAttribute(qkv_gemm, cudaFuncAttributeMaxDynamicSharedMemorySize, GEMM_SMEM);
    cudaFuncSetAttribute(out_gemm, cudaFuncAttributeMaxDynamicSharedMemorySize, GEMM_SMEM);
    cudaFuncSetAttribute(av_kernel, cudaFuncAttributeMaxDynamicSharedMemorySize, AV_SMEM);

    add_kernel<<<TB * Dq / 1024, 256>>>(inp, pe);
    round_wq<<<Dq * N3 / 1024, 256>>>(Wqkv);
    round_wo<<<ND * ND / 1024, 256>>>(Wo);
    qkv_gemm<<<dim3(N3 / 128, TB / 128), 256, GEMM_SMEM>>>();
    score_kernel<<<dim3(136, ZN), 256>>>();
    softmax_kernel<<<ZN * Tq, 128>>>();
    coverage_kernel<<<dim3(Tq / 32, Tq / 32, Bq), 256>>>(out_cov);
    av_kernel<<<dim3(Tq / 64, ZN), 256, AV_SMEM>>>();
    out_gemm<<<dim3(ND / 128, TB / 128), 256, GEMM_SMEM>>>(out_attn);
}

// round 9
// speedup vs baseline: 1.2523x; 1.0370x over previous
#include <cuda_runtime.h>
#include <stdint.h>
#include <math.h>

#define Tq 1024
#define Bq 8
#define Dq 1024
#define NH 16
#define DH 64
#define TB (Tq*Bq)       /* 8192 rows */
#define ND (NH*DH)       /* 1024 */
#define N3 (3*ND)        /* 3072 */
#define ZN (Bq*NH)       /* 128 */

// ---- static scratch (zero-initialized; masked region of g_S never written) ----
// k-dim of GEMM operands stored PAIR-PERMUTED within 8-groups:
//   stored order [0,4,1,5,2,6,3,7]  =>  orig (k, k+4) adjacent => LDS.64 frags.
__device__ float g_x[(size_t)TB*Dq];        // rounded x, k-permuted
__device__ float g_wqT[(size_t)N3*Dq];      // rounded W_qkv^T [n][k], k-permuted
__device__ float g_woT[(size_t)ND*ND];      // rounded W_o^T  [n][k], k-permuted
__device__ float g_q[(size_t)ZN*Tq*DH];     // rounded, [b][n][t][d], d-permuted
__device__ float g_k[(size_t)ZN*Tq*DH];     // rounded, d-permuted
__device__ float g_v[(size_t)ZN*Tq*DH];     // rounded, natural d
__device__ float g_av[(size_t)TB*ND];       // [t*B+b][col], col-permuted
__device__ float g_S[(size_t)ZN*Tq*Tq];     // fp32 probs, [z][i][j] (masked = 0)

// ---- helpers ----
__device__ __forceinline__ uint32_t f2tf(float x) {
    uint32_t y;
    asm("cvt.rna.tf32.f32 %0, %1;" : "=r"(y) : "f"(x));
    return y;
}
__device__ __forceinline__ float f2tf_f(float x) { return __uint_as_float(f2tf(x)); }
__device__ __forceinline__ int perm8(int x) { return 2 * (x & 3) + (x >> 2); } // x in 0..7
__device__ __forceinline__ void mma8(float c[4],
                                     uint32_t a0, uint32_t a1, uint32_t a2, uint32_t a3,
                                     uint32_t b0, uint32_t b1) {
    asm volatile("mma.sync.aligned.m16n8k8.row.col.f32.tf32.tf32.f32 "
                 "{%0,%1,%2,%3}, {%4,%5,%6,%7}, {%8,%9}, {%0,%1,%2,%3};\n"
                 : "+f"(c[0]), "+f"(c[1]), "+f"(c[2]), "+f"(c[3])
                 : "r"(a0), "r"(a1), "r"(a2), "r"(a3), "r"(b0), "r"(b1));
}
#define CP16(dst_u32, src_ptr) \
    asm volatile("cp.async.cg.shared.global [%0], [%1], 16;\n" :: "r"(dst_u32), "l"(src_ptr))
#define CP_COMMIT() asm volatile("cp.async.commit_group;\n")
#define CP_WAIT(n)  asm volatile("cp.async.wait_group %0;\n" :: "n"(n))

// ============================================================================
// x = tf32(input + pos_enc), stored with k-pair permutation. 8 elems/thread.
// stored[0..7] = orig[0,4,1,5,2,6,3,7]
// ============================================================================
__global__ __launch_bounds__(256) void add_kernel(const float* __restrict__ a,
                                                  const float* __restrict__ b) {
    size_t i = ((size_t)blockIdx.x * 256 + threadIdx.x) * 8;
    float4 a0 = *(const float4*)(a + i),     a1 = *(const float4*)(a + i + 4);
    float4 b0 = *(const float4*)(b + i),     b1 = *(const float4*)(b + i + 4);
    float r0 = f2tf_f(a0.x + b0.x), r1 = f2tf_f(a0.y + b0.y);
    float r2 = f2tf_f(a0.z + b0.z), r3 = f2tf_f(a0.w + b0.w);
    float r4 = f2tf_f(a1.x + b1.x), r5 = f2tf_f(a1.y + b1.y);
    float r6 = f2tf_f(a1.z + b1.z), r7 = f2tf_f(a1.w + b1.w);
    float4 o0 = {r0, r4, r1, r5};
    float4 o1 = {r2, r6, r3, r7};
    *(float4*)(g_x + i) = o0;
    *(float4*)(g_x + i + 4) = o1;
}

// ============================================================================
// Transpose + round + k-permute weights:  dst[n][k'] = tf32(src[k][n])
// 32x32 tiles, 256 threads.
// ============================================================================
template<int NCOLS>
__device__ __forceinline__ void transpose_round(const float* __restrict__ src,
                                                float* __restrict__ dst) {
    __shared__ float sm[32][33];
    const int t = threadIdx.x;
    const int k0 = blockIdx.y * 32, n0 = blockIdx.x * 32;
    {
        int kk = t >> 3, nn = (t & 7) * 4;
        float4 v = *(const float4*)(src + (size_t)(k0 + kk) * NCOLS + n0 + nn);
        sm[kk][nn] = v.x; sm[kk][nn + 1] = v.y; sm[kk][nn + 2] = v.z; sm[kk][nn + 3] = v.w;
    }
    __syncthreads();
    {
        int nrow = t >> 3;
        int q = t & 7, gg = q >> 1, h = q & 1;
        int o0 = h ? 2 : 0, o1 = h ? 6 : 4, o2 = h ? 3 : 1, o3 = h ? 7 : 5;
        int kb = gg * 8;
        float4 o;
        o.x = f2tf_f(sm[kb + o0][nrow]);
        o.y = f2tf_f(sm[kb + o1][nrow]);
        o.z = f2tf_f(sm[kb + o2][nrow]);
        o.w = f2tf_f(sm[kb + o3][nrow]);
        *(float4*)(dst + (size_t)(n0 + nrow) * 1024 + k0 + kb + h * 4) = o;
    }
}
__global__ __launch_bounds__(256) void round_wq(const float* __restrict__ src) {
    transpose_round<N3>(src, g_wqT);
}
__global__ __launch_bounds__(256) void round_wo(const float* __restrict__ src) {
    transpose_round<ND>(src, g_woT);
}

// ============================================================================
// tf32 GEMM body, cp.async 2-stage, LDS.64 pair fragments.
// A tile [128 rows][32 k'] stride 40; B tile [128 n][32 k'] stride 40.
// Stride 40 (==8 mod 32): per half-warp banks 8g+2tg all distinct.
// ============================================================================
#define T_STG 5120   /* 128*40 floats per stage (A or B) */
#define NSTG  2
#define GEMM_SMEM (NSTG * 2 * T_STG * 4)   /* 81920 bytes */

struct GemmFrag { float acc[4][4][4]; };

__device__ __forceinline__ void gemm_issue(uint32_t aB, uint32_t bB, int s,
                                           const float* __restrict__ Ag,
                                           const float* __restrict__ Bg,
                                           int ldA, int ldB, int m0, int n0, int k0,
                                           int tx) {
#pragma unroll
    for (int p = 0; p < 4; p++) {
        int chunk = tx + p * 256;
        int row = chunk >> 3;
        int coff = (chunk & 7) * 4;
        CP16(aB + (uint32_t)(s * T_STG + row * 40 + coff) * 4u,
             Ag + (size_t)(m0 + row) * ldA + k0 + coff);
        CP16(bB + (uint32_t)(s * T_STG + row * 40 + coff) * 4u,
             Bg + (size_t)(n0 + row) * ldB + k0 + coff);
    }
}

__device__ __forceinline__ void gemm_compute(GemmFrag& F, const uint32_t* Asm,
                                             const uint32_t* Bsm, int s,
                                             int wm, int wn, int g, int tg) {
    const uint32_t* A = Asm + s * T_STG;
    const uint32_t* B = Bsm + s * T_STG;
#pragma unroll
    for (int ks = 0; ks < 32; ks += 8) {
        uint32_t a[4][4], b[4][2];
#pragma unroll
        for (int mi = 0; mi < 4; mi++) {
            int r = wm + mi * 16 + g;
            uint2 p0 = *(const uint2*)&A[r * 40 + ks + 2 * tg];
            uint2 p1 = *(const uint2*)&A[(r + 8) * 40 + ks + 2 * tg];
            a[mi][0] = p0.x; a[mi][2] = p0.y;
            a[mi][1] = p1.x; a[mi][3] = p1.y;
        }
#pragma unroll
        for (int ni = 0; ni < 4; ni++) {
            int c = wn + ni * 8 + g;
            uint2 pb = *(const uint2*)&B[c * 40 + ks + 2 * tg];
            b[ni][0] = pb.x; b[ni][1] = pb.y;
        }
#pragma unroll
        for (int mi = 0; mi < 4; mi++)
#pragma unroll
            for (int ni = 0; ni < 4; ni++)
                mma8(F.acc[mi][ni], a[mi][0], a[mi][1], a[mi][2], a[mi][3],
                     b[ni][0], b[ni][1]);
    }
}

#define GEMM_MAINLOOP(Ag, Bg, ldA, ldB)                                         \
    gemm_issue(aB, bB, 0, Ag, Bg, ldA, ldB, m0, n0, 0, tx);                     \
    CP_COMMIT();                                                                \
    { int buf = 0;                                                              \
    _Pragma("unroll 1")                                                         \
    for (int it = 0; it < 32; it++) {                                           \
        if (it + 1 < 32) {                                                      \
            gemm_issue(aB, bB, buf ^ 1, Ag, Bg, ldA, ldB, m0, n0,               \
                       (it + 1) * 32, tx);                                      \
            CP_COMMIT();                                                        \
            CP_WAIT(1);                                                         \
        } else {                                                                \
            CP_WAIT(0);                                                         \
        }                                                                       \
        __syncthreads();                                                        \
        gemm_compute(F, Asm, Bsm, buf, wm, wn, g, tg);                          \
        __syncthreads();                                                        \
        buf ^= 1;                                                               \
    } }

// ============================================================================
// QKV GEMM: [8192,3072] = g_x @ g_wqT^T; epilogue scatters rounded Q/K/V
// (Q,K with d-permutation for score's LDS.64 frags; V natural).
// ============================================================================
__global__ __launch_bounds__(256, 2) void qkv_gemm() {
    extern __shared__ float sm[];
    const uint32_t* Asm = (const uint32_t*)sm;
    const uint32_t* Bsm = (const uint32_t*)(sm + NSTG * T_STG);
    uint32_t aB = (uint32_t)__cvta_generic_to_shared(sm);
    uint32_t bB = (uint32_t)__cvta_generic_to_shared(sm + NSTG * T_STG);
    const int tx = threadIdx.x;
    const int warp = tx >> 5, lane = tx & 31;
    const int g = lane >> 2, tg = lane & 3;
    const int wm = (warp >> 2) * 64, wn = (warp & 3) * 32;
    const int m0 = blockIdx.y * 128, n0 = blockIdx.x * 128;

    GemmFrag F;
#pragma unroll
    for (int mi = 0; mi < 4; mi++)
#pragma unroll
        for (int ni = 0; ni < 4; ni++)
#pragma unroll
            for (int r = 0; r < 4; r++) F.acc[mi][ni][r] = 0.f;

    GEMM_MAINLOOP(g_x, g_wqT, Dq, Dq)

#pragma unroll
    for (int mi = 0; mi < 4; mi++)
#pragma unroll
        for (int ni = 0; ni < 4; ni++)
#pragma unroll
            for (int rr = 0; rr < 2; rr++) {
                int row = m0 + wm + mi * 16 + g + rr * 8;
                int b = row & 7, t = row >> 3;
#pragma unroll
                for (int cc = 0; cc < 2; cc++) {
                    int col = n0 + wn + ni * 8 + 2 * tg + cc;
                    int part = col >> 10;
                    int rem = col & 1023;
                    int n = rem >> 6, d = rem & 63;
                    float val = f2tf_f(F.acc[mi][ni][rr * 2 + cc]);
                    size_t base = ((size_t)((b << 4) + n) * Tq + t) * DH;
                    if (part == 0)       g_q[base + (d & ~7) + perm8(d & 7)] = val;
                    else if (part == 1)  g_k[base + (d & ~7) + perm8(d & 7)] = val;
                    else                 g_v[base + d] = val;
                }
            }
}

// ============================================================================
// Output projection: out[8192,1024] = g_av @ g_woT^T (both k-permuted).
// ============================================================================
__global__ __launch_bounds__(256, 2) void out_gemm(float* __restrict__ out) {
    extern __shared__ float sm[];
    const uint32_t* Asm = (const uint32_t*)sm;
    const uint32_t* Bsm = (const uint32_t*)(sm + NSTG * T_STG);
    uint32_t aB = (uint32_t)__cvta_generic_to_shared(sm);
    uint32_t bB = (uint32_t)__cvta_generic_to_shared(sm + NSTG * T_STG);
    const int tx = threadIdx.x;
    const int warp = tx >> 5, lane = tx & 31;
    const int g = lane >> 2, tg = lane & 3;
    const int wm = (warp >> 2) * 64, wn = (warp & 3) * 32;
    const int m0 = blockIdx.y * 128, n0 = blockIdx.x * 128;

    GemmFrag F;
#pragma unroll
    for (int mi = 0; mi < 4; mi++)
#pragma unroll
        for (int ni = 0; ni < 4; ni++)
#pragma unroll
            for (int r = 0; r < 4; r++) F.acc[mi][ni][r] = 0.f;

    GEMM_MAINLOOP(g_av, g_woT, ND, ND)

#pragma unroll
    for (int mi = 0; mi < 4; mi++)
#pragma unroll
        for (int ni = 0; ni < 4; ni++)
#pragma unroll
            for (int rr = 0; rr < 2; rr++) {
                int row = m0 + wm + mi * 16 + g + rr * 8;
#pragma unroll
                for (int cc = 0; cc < 2; cc++) {
                    int col = n0 + wn + ni * 8 + 2 * tg + cc;
                    out[(size_t)row * ND + col] = F.acc[mi][ni][rr * 2 + cc];
                }
            }
}

// ============================================================================
// Scores: S = 0.125*Q@K^T, causal tiles. Q/K pre-rounded + d-permuted ->
// pure uint4 smem copies, LDS.64 fragments. Stride 72 (==8 mod 32).
// ============================================================================
__global__ __launch_bounds__(256) void score_kernel() {
    const int z = blockIdx.y;
    const int p = blockIdx.x;
    int ti = 0;
    while ((ti + 1) * (ti + 2) / 2 <= p) ti++;
    const int tj = p - ti * (ti + 1) / 2;

    __shared__ __align__(16) uint32_t Qs[64][72];
    __shared__ __align__(16) uint32_t Ks[64][72];
    const int tx = threadIdx.x;
    const int warp = tx >> 5, lane = tx & 31;
    const int g = lane >> 2, tg = lane & 3;
    const int wm = (warp >> 2) * 32;
    const int wn = (warp & 3) * 16;

    const int lr = tx >> 2, lc0 = (tx & 3) << 2;
    const float* qb = g_q + ((size_t)z * Tq + ti * 64) * DH;
    const float* kb = g_k + ((size_t)z * Tq + tj * 64) * DH;
#pragma unroll
    for (int rr = 0; rr < 4; rr++) {
        int c = lc0 + rr * 16;
        *(uint4*)&Qs[lr][c] = *(const uint4*)(qb + lr * DH + c);
        *(uint4*)&Ks[lr][c] = *(const uint4*)(kb + lr * DH + c);
    }
    __syncthreads();

    float acc[2][2][4];
#pragma unroll
    for (int mi = 0; mi < 2; mi++)
#pragma unroll
        for (int ni = 0; ni < 2; ni++)
#pragma unroll
            for (int r = 0; r < 4; r++) acc[mi][ni][r] = 0.f;

#pragma unroll
    for (int ks = 0; ks < 64; ks += 8) {
        uint32_t a[2][4], b[2][2];
#pragma unroll
        for (int mi = 0; mi < 2; mi++) {
            int r = wm + mi * 16 + g;
            uint2 p0 = *(const uint2*)&Qs[r][ks + 2 * tg];
            uint2 p1 = *(const uint2*)&Qs[r + 8][ks + 2 * tg];
            a[mi][0] = p0.x; a[mi][2] = p0.y;
            a[mi][1] = p1.x; a[mi][3] = p1.y;
        }
#pragma unroll
        for (int ni = 0; ni < 2; ni++) {
            int c = wn + ni * 8 + g;
            uint2 pb = *(const uint2*)&Ks[c][ks + 2 * tg];
            b[ni][0] = pb.x; b[ni][1] = pb.y;
        }
#pragma unroll
        for (int mi = 0; mi < 2; mi++)
#pragma unroll
            for (int ni = 0; ni < 2; ni++)
                mma8(acc[mi][ni], a[mi][0], a[mi][1], a[mi][2], a[mi][3],
                     b[ni][0], b[ni][1]);
    }

    const float scale = 0.125f;
#pragma unroll
    for (int mi = 0; mi < 2; mi++)
#pragma unroll
        for (int ni = 0; ni < 2; ni++)
#pragma unroll
            for (int rr = 0; rr < 2; rr++) {
                int i = ti * 64 + wm + mi * 16 + g + rr * 8;
#pragma unroll
                for (int cc = 0; cc < 2; cc++) {
                    int j = tj * 64 + wn + ni * 8 + 2 * tg + cc;
                    if (j <= i)
                        g_S[((size_t)z * Tq + i) * Tq + j] = acc[mi][ni][rr * 2 + cc] * scale;
                }
            }
}

// ============================================================================
// Row softmax, vectorized + len-aware (threads beyond len skip loads).
// ============================================================================
__global__ __launch_bounds__(128) void softmax_kernel() {
    const int rid = blockIdx.x;
    const int i = rid & (Tq - 1);
    float* row = g_S + (size_t)rid * Tq;
    const int len = i + 1;
    const int tx = threadIdx.x;
    const int j0 = tx * 8;

    float vals[8];
    if (j0 < len) {
        float4 v0 = *(const float4*)(row + j0);
        float4 v1 = *(const float4*)(row + j0 + 4);
        vals[0] = v0.x; vals[1] = v0.y; vals[2] = v0.z; vals[3] = v0.w;
        vals[4] = v1.x; vals[5] = v1.y; vals[6] = v1.z; vals[7] = v1.w;
    } else {
#pragma unroll
        for (int u = 0; u < 8; u++) vals[u] = -1e30f;
    }

    float m = -1e30f;
#pragma unroll
    for (int u = 0; u < 8; u++)
        if (j0 + u < len) m = fmaxf(m, vals[u]);

    __shared__ float redm[4];
    __shared__ float reds[4];
#pragma unroll
    for (int o = 16; o; o >>= 1) m = fmaxf(m, __shfl_xor_sync(0xffffffffu, m, o));
    if ((tx & 31) == 0) redm[tx >> 5] = m;
    __syncthreads();
    m = fmaxf(fmaxf(redm[0], redm[1]), fmaxf(redm[2], redm[3]));

    float s = 0.f;
#pragma unroll
    for (int u = 0; u < 8; u++) {
        float e = __expf(vals[u] - m);
        vals[u] = e;
        if (j0 + u < len) s += e;
    }
#pragma unroll
    for (int o = 16; o; o >>= 1) s += __shfl_xor_sync(0xffffffffu, s, o);
    if ((tx & 31) == 0) reds[tx >> 5] = s;
    __syncthreads();
    s = reds[0] + reds[1] + reds[2] + reds[3];
    const float inv = 1.0f / s;

    if (j0 + 8 <= len) {
        float4 o0, o1;
        o0.x = vals[0] * inv; o0.y = vals[1] * inv; o0.z = vals[2] * inv; o0.w = vals[3] * inv;
        o1.x = vals[4] * inv; o1.y = vals[5] * inv; o1.z = vals[6] * inv; o1.w = vals[7] * inv;
        *(float4*)(row + j0) = o0;
        *(float4*)(row + j0 + 4) = o1;
    } else if (j0 < len) {
#pragma unroll
        for (int u = 0; u < 8; u++)
            if (j0 + u < len) row[j0 + u] = vals[u] * inv;
    }
}

// ============================================================================
// Coverage: out[b][j][i] = mean_n prob[b][n][i][j]. (unchanged)
// ============================================================================
__global__ __launch_bounds__(256) void coverage_kernel(float* __restrict__ out_cov) {
    const int b = blockIdx.z;
    const int i0 = blockIdx.y * 32, j0 = blockIdx.x * 32;
    const int tx = threadIdx.x;

    if (j0 >= i0 + 32) {
#pragma unroll
        for (int it = 0; it < 4; it++) {
            int idx = tx + it * 256;
            int jj = idx >> 5, ii = idx & 31;
            out_cov[((size_t)b * Tq + j0 + jj) * Tq + i0 + ii] = 0.f;
        }
        return;
    }

    __shared__ float cs[32][33];
#pragma unroll
    for (int it = 0; it < 4; it++) {
        int idx = tx + it * 256;
        int ii = idx >> 5, jj = idx & 31;
        float s = 0.f;
#pragma unroll
        for (int n = 0; n < 16; n++)
            s += g_S[(((size_t)(b * 16 + n) * Tq + i0 + ii) * Tq) + j0 + jj];
        cs[ii][jj] = s * (1.0f / 16.0f);
    }
    __syncthreads();
#pragma unroll
    for (int it = 0; it < 4; it++) {
        int idx = tx + it * 256;
        int jj = idx >> 5, ii = idx & 31;
        out_cov[((size_t)b * Tq + j0 + jj) * Tq + i0 + ii] = cs[ii][jj];
    }
}

// ============================================================================
// PV: attn_vec = P @ V, cp.async 2-stage (R8-identical math);
// epilogue writes g_av with col-permutation for out_gemm's k-frags.
// ============================================================================
#define AVP 4352   /* 64*68 floats per stage */
#define AVV 4608   /* 64*72 floats per stage */
#define AV_SMEM ((2*AVP + 2*AVV) * 4)   /* 71680 bytes */

__global__ __launch_bounds__(256, 2) void av_kernel() {
    extern __shared__ float sm[];
    float* Pf = sm;
    float* Vf = sm + 2 * AVP;
    uint32_t pB = (uint32_t)__cvta_generic_to_shared(Pf);
    uint32_t vB = (uint32_t)__cvta_generic_to_shared(Vf);

    const int ti = (Tq / 64 - 1) - blockIdx.x;   // heavy tiles first
    const int z = blockIdx.y;
    const int bq = z >> 4, nh = z & 15;
    const int tx = threadIdx.x;
    const int warp = tx >> 5, lane = tx & 31;
    const int g = lane >> 2, tg = lane & 3;
    const int wm = (warp >> 2) * 32;
    const int wn = (warp & 3) * 16;

    const int lrow = tx >> 2, lcol = (tx & 3) * 16;
    const float* pbase = g_S + ((size_t)z * Tq + ti * 64 + lrow) * Tq + lcol;
    const float* vbase = g_v + ((size_t)z * Tq + lrow) * DH + lcol;

    const int nj = ti + 1;

    float acc[2][2][4];
#pragma unroll
    for (int mi = 0; mi < 2; mi++)
#pragma unroll
        for (int ni = 0; ni < 2; ni++)
#pragma unroll
            for (int r = 0; r < 4; r++) acc[mi][ni][r] = 0.f;

#pragma unroll
    for (int q = 0; q < 4; q++) {
        CP16(pB + (uint32_t)(lrow * 68 + lcol + q * 4) * 4u, pbase + q * 4);
        CP16(vB + (uint32_t)(lrow * 72 + lcol + q * 4) * 4u, vbase + q * 4);
    }
    CP_COMMIT();

    int buf = 0;
#pragma unroll 1
    for (int jt = 0; jt < nj; jt++) {
        if (jt + 1 < nj) {
            int s = buf ^ 1;
            int jn = jt + 1;
#pragma unroll
            for (int q = 0; q < 4; q++) {
                CP16(pB + (uint32_t)(s * AVP + lrow * 68 + lcol + q * 4) * 4u,
                     pbase + jn * 64 + q * 4);
                CP16(vB + (uint32_t)(s * AVV + lrow * 72 + lcol + q * 4) * 4u,
                     vbase + (size_t)jn * 64 * DH + q * 4);
            }
            CP_COMMIT();
            CP_WAIT(1);
        } else {
            CP_WAIT(0);
        }
        __syncthreads();

        const float* P = Pf + buf * AVP;
        const float* V = Vf + buf * AVV;
#pragma unroll
        for (int ks = 0; ks < 64; ks += 8) {
            uint32_t a[2][4], b[2][2];
#pragma unroll
            for (int mi = 0; mi < 2; mi++) {
                int r = wm + mi * 16 + g;
                a[mi][0] = f2tf(P[r * 68 + ks + tg]);
                a[mi][1] = f2tf(P[(r + 8) * 68 + ks + tg]);
                a[mi][2] = f2tf(P[r * 68 + ks + tg + 4]);
                a[mi][3] = f2tf(P[(r + 8) * 68 + ks + tg + 4]);
            }
#pragma unroll
            for (int ni = 0; ni < 2; ni++) {
                int c = wn + ni * 8 + g;
                b[ni][0] = f2tf(V[(ks + tg) * 72 + c]);
                b[ni][1] = f2tf(V[(ks + tg + 4) * 72 + c]);
            }
#pragma unroll
            for (int mi = 0; mi < 2; mi++)
#pragma unroll
                for (int ni = 0; ni < 2; ni++)
                    mma8(acc[mi][ni], a[mi][0], a[mi][1], a[mi][2], a[mi][3],
                         b[ni][0], b[ni][1]);
        }
        __syncthreads();
        buf ^= 1;
    }

#pragma unroll
    for (int mi = 0; mi < 2; mi++)
#pragma unroll
        for (int ni = 0; ni < 2; ni++)
#pragma unroll
            for (int rr = 0; rr < 2; rr++) {
                int i = ti * 64 + wm + mi * 16 + g + rr * 8;
#pragma unroll
                for (int cc = 0; cc < 2; cc++) {
                    int d = wn + ni * 8 + 2 * tg + cc;
                    int dp = (d & ~7) + perm8(d & 7);
                    g_av[((size_t)(i * Bq + bq)) * ND + nh * 64 + dp] = acc[mi][ni][rr * 2 + cc];
                }
            }
}

// ============================================================================
extern "C" void kernel_launch(void* const* d_in, const int* in_sizes, int n_in,
                              void* d_out, int out_size) {
    const float* inp  = (const float*)d_in[0];
    const float* pe   = (const float*)d_in[1];
    const float* Wqkv = (const float*)d_in[3];
    const float* Wo   = (const float*)d_in[4];

    float* out_attn = (float*)d_out;
    float* out_cov  = out_attn + (size_t)TB * ND;

    cudaFuncSetAttribute(qkv_gemm, cudaFuncAttributeMaxDynamicSharedMemorySize, GEMM_SMEM);
    cudaFuncSetAttribute(out_gemm, cudaFuncAttributeMaxDynamicSharedMemorySize, GEMM_SMEM);
    cudaFuncSetAttribute(av_kernel, cudaFuncAttributeMaxDynamicSharedMemorySize, AV_SMEM);

    add_kernel<<<TB * Dq / 2048, 256>>>(inp, pe);
    round_wq<<<dim3(N3 / 32, Dq / 32), 256>>>(Wqkv);
    round_wo<<<dim3(ND / 32, ND / 32), 256>>>(Wo);
    qkv_gemm<<<dim3(N3 / 128, TB / 128), 256, GEMM_SMEM>>>();
    score_kernel<<<dim3(136, ZN), 256>>>();
    softmax_kernel<<<ZN * Tq, 128>>>();
    coverage_kernel<<<dim3(Tq / 32, Tq / 32, Bq), 256>>>(out_cov);
    av_kernel<<<dim3(Tq / 64, ZN), 256, AV_SMEM>>>();
    out_gemm<<<dim3(ND / 128, TB / 128), 256, GEMM_SMEM>>>(out_attn);
}